// round 9
// baseline (speedup 1.0000x reference)
#include <cuda_runtime.h>
#include <cuda_bf16.h>
#include <cstdint>
#include <cstddef>

#define N_USER 50000
#define N_ITEM 20000
#define D_IN   128
#define D_HID  256
#define D_OUT  128
#define NE     300000
#define NL     200000

#define XU_ELEMS (N_USER * D_IN)
#define X_ELEMS  ((N_USER + N_ITEM) * D_IN)
#define H_OFF_I  (N_USER * D_HID)

// ---------------- device scratch (static, allocation-free) ----------------
__device__ float g_deg_user[N_USER];
__device__ float g_deg_item[N_ITEM];
__device__ float g_agg1_item[N_ITEM * D_IN];   // later reused as p_item
__device__ float g_agg1_user[N_USER * D_IN];   // later reused as p_user
__device__ float g_acc2_item[N_ITEM * D_OUT];
__device__ float g_acc2_user[N_USER * D_OUT];
__device__ float g_z_item[N_ITEM * D_OUT];
__device__ float g_z_user[N_USER * D_OUT];
// pre-split operands (bf16 hi/lo)
__device__ __nv_bfloat16 g_whi[8 * 32768];
__device__ __nv_bfloat16 g_wlo[8 * 32768];
__device__ __nv_bfloat16 g_xhi[X_ELEMS];
__device__ __nv_bfloat16 g_xlo[X_ELEMS];
__device__ __nv_bfloat16 g_hhi[(N_USER + N_ITEM) * D_HID];
__device__ __nv_bfloat16 g_hlo[(N_USER + N_ITEM) * D_HID];

// ---------------- helpers ----------------
__device__ __forceinline__ void split2(float x0, float x1, uint32_t& hi, uint32_t& lo) {
    __nv_bfloat162 h = __floats2bfloat162_rn(x0, x1);
    float r0 = x0 - __bfloat162float(__low2bfloat16(h));
    float r1 = x1 - __bfloat162float(__high2bfloat16(h));
    __nv_bfloat162 l = __floats2bfloat162_rn(r0, r1);
    hi = *reinterpret_cast<uint32_t*>(&h);
    lo = *reinterpret_cast<uint32_t*>(&l);
}

// ---------------- fused zero fill ----------------
__global__ void zero_multi6(float4* p0, int n0, float4* p1, int n1,
                            float4* p2, int n2, float4* p3, int n3,
                            float4* p4, int n4, float4* p5, int n5) {
    int i = blockIdx.x * blockDim.x + threadIdx.x;
    float4 z = make_float4(0.f, 0.f, 0.f, 0.f);
    if (i < n0) p0[i] = z;
    if (i < n1) p1[i] = z;
    if (i < n2) p2[i] = z;
    if (i < n3) p3[i] = z;
    if (i < n4) p4[i] = z;
    if (i < n5) p5[i] = z;
}

// ---------------- split weights + x features to bf16 hi/lo (one launch) -----
#define W_WORK (8 * 32768)
#define X_WORK (X_ELEMS / 4)
__global__ void split_all(const float* w0, const float* w1, const float* w2,
                          const float* w3, const float* w4, const float* w5,
                          const float* w6, const float* w7,
                          const float* xu, const float* xi) {
    int i = blockIdx.x * blockDim.x + threadIdx.x;
    if (i < W_WORK) {
        int w = i >> 15;
        int e = i & 32767;
        const float* src;
        switch (w) {
            case 0: src = w0; break;
            case 1: src = w1; break;
            case 2: src = w2; break;
            case 3: src = w3; break;
            case 4: src = w4; break;
            case 5: src = w5; break;
            case 6: src = w6; break;
            default: src = w7; break;
        }
        float v = src[e];
        __nv_bfloat16 h = __float2bfloat16(v);
        g_whi[i] = h;
        g_wlo[i] = __float2bfloat16(v - __bfloat162float(h));
    } else {
        int j = i - W_WORK;
        if (j < X_WORK) {
            int f = j * 4;
            const float* src = (f < XU_ELEMS) ? (xu + f) : (xi + (f - XU_ELEMS));
            float4 v = *(const float4*)src;
            uint32_t h0, l0, h1, l1;
            split2(v.x, v.y, h0, l0);
            split2(v.z, v.w, h1, l1);
            ((uint2*)g_xhi)[j] = make_uint2(h0, h1);
            ((uint2*)g_xlo)[j] = make_uint2(l0, l1);
        }
    }
}

// ---------------- vectorized global reduction ----------------
__device__ __forceinline__ void red_add_v4(float* p, float4 v) {
    asm volatile("red.global.add.v4.f32 [%0], {%1, %2, %3, %4};"
                 :: "l"(p), "f"(v.x), "f"(v.y), "f"(v.z), "f"(v.w)
                 : "memory");
}

// ---------------- layer-1 edge scatter (128-dim) + degree count ----------------
__global__ void scatter_l1(const float* __restrict__ x_user,
                           const float* __restrict__ x_item,
                           const int* __restrict__ src,
                           const int* __restrict__ dst) {
    int gt = blockIdx.x * blockDim.x + threadIdx.x;
    int e = gt >> 5;
    int lane = gt & 31;
    if (e >= NE) return;
    int s = __ldg(src + e);
    int d = __ldg(dst + e);

    float4 vu = __ldg(&((const float4*)x_user)[s * 32 + lane]);
    red_add_v4(g_agg1_item + d * 128 + lane * 4, vu);

    float4 vi = __ldg(&((const float4*)x_item)[d * 32 + lane]);
    red_add_v4(g_agg1_user + s * 128 + lane * 4, vi);

    if (lane == 0) {
        atomicAdd(&g_deg_item[d], 1.f);
        atomicAdd(&g_deg_user[s], 1.f);
    }
}

// ---------------- layer-2 scatter of transformed features (128-dim) ----------------
__global__ void scatter_p(const int* __restrict__ src,
                          const int* __restrict__ dst) {
    int gt = blockIdx.x * blockDim.x + threadIdx.x;
    int e = gt >> 5;
    int lane = gt & 31;
    if (e >= NE) return;
    int s = __ldg(src + e);
    int d = __ldg(dst + e);

    float4 pu = __ldg(&((const float4*)g_agg1_user)[s * 32 + lane]);
    red_add_v4(g_acc2_item + d * 128 + lane * 4, pu);

    float4 pi = __ldg(&((const float4*)g_agg1_item)[d * 32 + lane]);
    red_add_v4(g_acc2_user + s * 128 + lane * 4, pi);
}

// ================= 3xBF16 mma.sync GEMM: frag-major A, R6 B layout =========
__device__ __forceinline__ void mma_bf16(float c[4],
                                         const uint32_t a[4],
                                         const uint32_t b[2]) {
    asm volatile(
        "mma.sync.aligned.m16n8k16.row.col.f32.bf16.bf16.f32 "
        "{%0,%1,%2,%3}, {%4,%5,%6,%7}, {%8,%9}, {%0,%1,%2,%3};"
        : "+f"(c[0]), "+f"(c[1]), "+f"(c[2]), "+f"(c[3])
        : "r"(a[0]), "r"(a[1]), "r"(a[2]), "r"(a[3]), "r"(b[0]), "r"(b[1]));
}

struct GP {
    int M[2];
    const float* Af[2];                 // fp32 A for seg0 (SEG2 only)
    const __nv_bfloat16* Ah[2];         // pre-split A
    const __nv_bfloat16* Al[2];
    const __nv_bfloat16* W1h[2];
    const __nv_bfloat16* W1l[2];
    const __nv_bfloat16* W2h[2];
    const __nv_bfloat16* W2l[2];
    const float* bias[2];
    const float* deg[2];
    const float* Cin[2];
    float* Cf[2];
    __nv_bfloat16* Ch[2];
    __nv_bfloat16* Cl[2];
};

template <int K, int N, bool SEG2, bool HASBIAS, bool CACC, bool RELU, bool OUTSPLIT>
__global__ __launch_bounds__(256, 2)
void gemm_pair3(GP P) {
    const int side = blockIdx.z;
    const int M = P.M[side];
    const int bm = blockIdx.y * 128;
    if (bm >= M) return;
    const int bn = blockIdx.x * 128;

    const float* __restrict__ Af = P.Af[side];
    const __nv_bfloat16* __restrict__ Ahp = P.Ah[side];
    const __nv_bfloat16* __restrict__ Alp = P.Al[side];
    const __nv_bfloat16* __restrict__ W1h = P.W1h[side];
    const __nv_bfloat16* __restrict__ W1l = P.W1l[side];
    const __nv_bfloat16* __restrict__ W2h = P.W2h[side];
    const __nv_bfloat16* __restrict__ W2l = P.W2l[side];
    const float* __restrict__ bias = P.bias[side];
    const float* __restrict__ deg = P.deg[side];
    const float* __restrict__ Cin = P.Cin[side];

    // A frag tuples: [wmblk 2][mt 4][fg 8][ft' 4][4 words] (R6 layout)
    __shared__ uint32_t AsH[2][1024];
    __shared__ uint32_t AsL[2][1024];
    // B pairs: [kp 8][n 136 pad] (R6 layout, conflict-free)
    __shared__ uint32_t BsH[2][8][136];
    __shared__ uint32_t BsL[2][8][136];

    const int tid = threadIdx.x;
    const int lane = tid & 31;
    const int w = tid >> 5;
    const int wmblk = w & 1;
    const int wm = wmblk * 64;
    const int wn = (w >> 1) * 32;
    const int fg = lane >> 2;
    const int ft = lane & 3;
    const int ftp = ft ^ ((fg >> 1) & 3);

    // ---- producer mappings ----
    const int arow = tid >> 1;
    const int khalf = tid & 1;
    const int am = bm + arow;
    const bool avalid = am < M;
    const int pwm = arow >> 6;
    const int pmt = (arow >> 4) & 3;
    const int pfg = arow & 7;
    const int prh = (arow >> 3) & 1;
    const int psw = (pfg >> 1) & 3;
    const int atbase = ((pwm * 4 + pmt) * 8 + pfg) * 16 + prh * 2 + khalf;
    const int kp = tid >> 5;
    const int n0 = lane * 4;
    // consumer A tuple base
    const int aidx = ((wmblk * 4) * 8 + fg) * 16;

    float ascale = 1.f;
    if (SEG2) ascale = avalid ? (1.f / fmaxf(__ldg(deg + am), 1.f)) : 0.f;

    float acc[4][4][4];
#pragma unroll
    for (int i = 0; i < 4; i++)
#pragma unroll
        for (int j = 0; j < 4; j++)
#pragma unroll
            for (int r = 0; r < 4; r++) acc[i][j][r] = 0.f;

    const int TPS = K / 16;
    const int NT = (SEG2 ? 2 : 1) * TPS;

    auto ldg_tile = [&](int t, bool& pres, float4& a0, float4& a1,
                        uint4& ah4, uint4& al4,
                        uint2& bh0, uint2& bh1, uint2& bl0, uint2& bl1) {
        const bool seg1 = SEG2 && (t >= TPS);
        pres = !SEG2 || seg1;
        const int k0 = (seg1 ? (t - TPS) : t) * 16;
        if (pres) {
            ah4 = make_uint4(0u, 0u, 0u, 0u);
            al4 = ah4;
            if (avalid) {
                ah4 = *(const uint4*)(Ahp + (size_t)am * K + k0 + khalf * 8);
                al4 = *(const uint4*)(Alp + (size_t)am * K + k0 + khalf * 8);
            }
        } else {
            a0 = make_float4(0.f, 0.f, 0.f, 0.f);
            a1 = a0;
            if (avalid) {
                const float* ap = Af + (size_t)am * K + k0 + khalf * 8;
                a0 = *(const float4*)ap;
                a1 = *(const float4*)(ap + 4);
                a0.x *= ascale; a0.y *= ascale; a0.z *= ascale; a0.w *= ascale;
                a1.x *= ascale; a1.y *= ascale; a1.z *= ascale; a1.w *= ascale;
            }
        }
        const __nv_bfloat16* Wh = seg1 ? W2h : W1h;
        const __nv_bfloat16* Wl = seg1 ? W2l : W1l;
        const __nv_bfloat16* wh = Wh + (size_t)(k0 + 2 * kp) * N + bn + n0;
        const __nv_bfloat16* wl = Wl + (size_t)(k0 + 2 * kp) * N + bn + n0;
        bh0 = *(const uint2*)wh;
        bh1 = *(const uint2*)(wh + N);
        bl0 = *(const uint2*)wl;
        bl1 = *(const uint2*)(wl + N);
    };

    auto sts_tile = [&](int s, bool pres, float4 a0, float4 a1,
                        uint4 ah4, uint4 al4,
                        uint2 bh0, uint2 bh1, uint2 bl0, uint2 bl1) {
        uint32_t hw[4], lw[4];
        if (pres) {
            hw[0] = ah4.x; hw[1] = ah4.y; hw[2] = ah4.z; hw[3] = ah4.w;
            lw[0] = al4.x; lw[1] = al4.y; lw[2] = al4.z; lw[3] = al4.w;
        } else {
            float f[8] = {a0.x, a0.y, a0.z, a0.w, a1.x, a1.y, a1.z, a1.w};
#pragma unroll
            for (int j = 0; j < 4; j++) split2(f[2 * j], f[2 * j + 1], hw[j], lw[j]);
        }
#pragma unroll
        for (int j = 0; j < 4; j++) {
            int widx = atbase + (j ^ psw) * 4;
            AsH[s][widx] = hw[j];
            AsL[s][widx] = lw[j];
        }
        // B: pack (k even, k odd) pairs for 4 consecutive n, 2 STS.128 (R6)
        uint4 ph, pl;
        ph.x = __byte_perm(bh0.x, bh1.x, 0x5410);
        ph.y = __byte_perm(bh0.x, bh1.x, 0x7632);
        ph.z = __byte_perm(bh0.y, bh1.y, 0x5410);
        ph.w = __byte_perm(bh0.y, bh1.y, 0x7632);
        pl.x = __byte_perm(bl0.x, bl1.x, 0x5410);
        pl.y = __byte_perm(bl0.x, bl1.x, 0x7632);
        pl.z = __byte_perm(bl0.y, bl1.y, 0x5410);
        pl.w = __byte_perm(bl0.y, bl1.y, 0x7632);
        *(uint4*)&BsH[s][kp][n0] = ph;
        *(uint4*)&BsL[s][kp][n0] = pl;
    };

    {
        bool pres; float4 a0, a1; uint4 ah4, al4; uint2 bh0, bh1, bl0, bl1;
        ldg_tile(0, pres, a0, a1, ah4, al4, bh0, bh1, bl0, bl1);
        sts_tile(0, pres, a0, a1, ah4, al4, bh0, bh1, bl0, bl1);
    }
    __syncthreads();

    int buf = 0;
    for (int t = 0; t < NT; t++) {
        const bool more = (t + 1) < NT;
        bool npres; float4 na0, na1; uint4 nah4, nal4; uint2 nbh0, nbh1, nbl0, nbl1;
        if (more) ldg_tile(t + 1, npres, na0, na1, nah4, nal4, nbh0, nbh1, nbl0, nbl1);

        // ---- A-hi frags: 4 x LDS.128 ----
        uint32_t ah[4][4];
#pragma unroll
        for (int mt = 0; mt < 4; mt++) {
            uint4 v = *(const uint4*)&AsH[buf][aidx + mt * 128 + ftp * 4];
            ah[mt][0] = v.x; ah[mt][1] = v.z; ah[mt][2] = v.y; ah[mt][3] = v.w;
        }
        // ---- B-hi frags: scalar LDS (R6) ----
        uint32_t bh[4][2];
#pragma unroll
        for (int nt = 0; nt < 4; nt++) {
            const int c = wn + 8 * nt + fg;
            bh[nt][0] = BsH[buf][ft][c];
            bh[nt][1] = BsH[buf][ft + 4][c];
        }
        // pass 1: Ah * Bh
#pragma unroll
        for (int mt = 0; mt < 4; mt++)
#pragma unroll
            for (int nt = 0; nt < 4; nt++) mma_bf16(acc[mt][nt], ah[mt], bh[nt]);

        // pass 2: Ah * Bl
        {
            uint32_t bl[4][2];
#pragma unroll
            for (int nt = 0; nt < 4; nt++) {
                const int c = wn + 8 * nt + fg;
                bl[nt][0] = BsL[buf][ft][c];
                bl[nt][1] = BsL[buf][ft + 4][c];
            }
#pragma unroll
            for (int mt = 0; mt < 4; mt++)
#pragma unroll
                for (int nt = 0; nt < 4; nt++) mma_bf16(acc[mt][nt], ah[mt], bl[nt]);
        }

        // pass 3: Al * Bh
        {
            uint32_t al[4][4];
#pragma unroll
            for (int mt = 0; mt < 4; mt++) {
                uint4 v = *(const uint4*)&AsL[buf][aidx + mt * 128 + ftp * 4];
                al[mt][0] = v.x; al[mt][1] = v.z; al[mt][2] = v.y; al[mt][3] = v.w;
            }
#pragma unroll
            for (int mt = 0; mt < 4; mt++)
#pragma unroll
                for (int nt = 0; nt < 4; nt++) mma_bf16(acc[mt][nt], al[mt], bh[nt]);
        }

        if (more) {
            sts_tile(buf ^ 1, npres, na0, na1, nah4, nal4, nbh0, nbh1, nbl0, nbl1);
            __syncthreads();
            buf ^= 1;
        }
    }

    // ---------------- epilogue ----------------
#pragma unroll
    for (int nt = 0; nt < 4; nt++) {
        const int c0 = bn + wn + 8 * nt + 2 * ft;
        float b0 = 0.f, b1 = 0.f;
        if (HASBIAS) {
            b0 = __ldg(bias + c0);
            b1 = __ldg(bias + c0 + 1);
        }
#pragma unroll
        for (int mt = 0; mt < 4; mt++) {
            const int r0 = bm + wm + 16 * mt + fg;
            const int r1 = r0 + 8;
            float o00 = acc[mt][nt][0] + b0;
            float o01 = acc[mt][nt][1] + b1;
            float o10 = acc[mt][nt][2] + b0;
            float o11 = acc[mt][nt][3] + b1;
            if (CACC) {
                if (r0 < M) {
                    float id0 = 1.f / fmaxf(__ldg(deg + r0), 1.f);
                    float2 ci = *(const float2*)(Cin + (size_t)r0 * N + c0);
                    o00 += ci.x * id0;
                    o01 += ci.y * id0;
                }
                if (r1 < M) {
                    float id1 = 1.f / fmaxf(__ldg(deg + r1), 1.f);
                    float2 ci = *(const float2*)(Cin + (size_t)r1 * N + c0);
                    o10 += ci.x * id1;
                    o11 += ci.y * id1;
                }
            }
            if (RELU) {
                o00 = fmaxf(o00, 0.f); o01 = fmaxf(o01, 0.f);
                o10 = fmaxf(o10, 0.f); o11 = fmaxf(o11, 0.f);
            }
            if (OUTSPLIT) {
                uint32_t hh, ll;
                if (r0 < M) {
                    split2(o00, o01, hh, ll);
                    ((uint32_t*)P.Ch[side])[((size_t)r0 * N + c0) >> 1] = hh;
                    ((uint32_t*)P.Cl[side])[((size_t)r0 * N + c0) >> 1] = ll;
                }
                if (r1 < M) {
                    split2(o10, o11, hh, ll);
                    ((uint32_t*)P.Ch[side])[((size_t)r1 * N + c0) >> 1] = hh;
                    ((uint32_t*)P.Cl[side])[((size_t)r1 * N + c0) >> 1] = ll;
                }
            } else {
                if (r0 < M)
                    *(float2*)(P.Cf[side] + (size_t)r0 * N + c0) = make_float2(o00, o01);
                if (r1 < M)
                    *(float2*)(P.Cf[side] + (size_t)r1 * N + c0) = make_float2(o10, o11);
            }
        }
    }
}

// ---------------- decode ----------------
__global__ void decode_kernel(const int* __restrict__ ls,
                              const int* __restrict__ ld,
                              float* __restrict__ out) {
    int gt = blockIdx.x * blockDim.x + threadIdx.x;
    int i = gt >> 5;
    int lane = gt & 31;
    if (i >= NL) return;
    int a = __ldg(ls + i);
    int b = __ldg(ld + i);
    float4 u = ((const float4*)g_z_user)[a * 32 + lane];
    float4 v = ((const float4*)g_z_item)[b * 32 + lane];
    float s = u.x * v.x + u.y * v.y + u.z * v.z + u.w * v.w;
#pragma unroll
    for (int o = 16; o > 0; o >>= 1) s += __shfl_down_sync(0xffffffffu, s, o);
    if (lane == 0) {
        out[i] = -s;
        out[NL + i] = s;
    }
}

// ---------------- host launch ----------------
extern "C" void kernel_launch(void* const* d_in, const int* in_sizes, int n_in,
                              void* d_out, int out_size) {
    const float* x_user = (const float*)d_in[0];
    const float* x_item = (const float*)d_in[1];
    const float* Wl1_ui = (const float*)d_in[2];
    const float* Wr1_ui = (const float*)d_in[3];
    const float* b1_ui  = (const float*)d_in[4];
    const float* Wl1_iu = (const float*)d_in[5];
    const float* Wr1_iu = (const float*)d_in[6];
    const float* b1_iu  = (const float*)d_in[7];
    const float* Wl2_ui = (const float*)d_in[8];
    const float* Wr2_ui = (const float*)d_in[9];
    const float* b2_ui  = (const float*)d_in[10];
    const float* Wl2_iu = (const float*)d_in[11];
    const float* Wr2_iu = (const float*)d_in[12];
    const float* b2_iu  = (const float*)d_in[13];
    const int* src_u     = (const int*)d_in[14];
    const int* dst_i     = (const int*)d_in[15];
    const int* label_src = (const int*)d_in[16];
    const int* label_dst = (const int*)d_in[17];

    float *deg_u, *deg_i, *a1i, *a1u, *c2i, *c2u, *zi, *zu;
    __nv_bfloat16 *whi, *wlo, *xhi, *xlo, *hhi, *hlo;
    cudaGetSymbolAddress((void**)&deg_u, g_deg_user);
    cudaGetSymbolAddress((void**)&deg_i, g_deg_item);
    cudaGetSymbolAddress((void**)&a1i, g_agg1_item);
    cudaGetSymbolAddress((void**)&a1u, g_agg1_user);
    cudaGetSymbolAddress((void**)&c2i, g_acc2_item);
    cudaGetSymbolAddress((void**)&c2u, g_acc2_user);
    cudaGetSymbolAddress((void**)&zi, g_z_item);
    cudaGetSymbolAddress((void**)&zu, g_z_user);
    cudaGetSymbolAddress((void**)&whi, g_whi);
    cudaGetSymbolAddress((void**)&wlo, g_wlo);
    cudaGetSymbolAddress((void**)&xhi, g_xhi);
    cudaGetSymbolAddress((void**)&xlo, g_xlo);
    cudaGetSymbolAddress((void**)&hhi, g_hhi);
    cudaGetSymbolAddress((void**)&hlo, g_hlo);

    const int MT_U = (N_USER + 127) / 128;   // 391

    // idx0: zero accumulators + degree counters
    {
        int n0 = N_ITEM * D_IN / 4, n1 = N_USER * D_IN / 4;
        int n2 = N_USER / 4, n3 = N_ITEM / 4;
        int n4 = N_ITEM * D_OUT / 4, n5 = N_USER * D_OUT / 4;
        zero_multi6<<<(n1 + 255) / 256, 256>>>((float4*)a1i, n0, (float4*)a1u, n1,
                                               (float4*)deg_u, n2, (float4*)deg_i, n3,
                                               (float4*)c2i, n4, (float4*)c2u, n5);
    }

    // idx1: split weights + x features
    {
        int total = W_WORK + X_WORK;
        split_all<<<(total + 255) / 256, 256>>>(Wl1_ui, Wr1_ui, Wl1_iu, Wr1_iu,
                                                Wl2_ui, Wr2_ui, Wl2_iu, Wr2_iu,
                                                x_user, x_item);
    }

    // idx2: layer-1 scatter + degrees
    {
        long long threads = (long long)NE * 32;
        scatter_l1<<<(int)((threads + 255) / 256), 256>>>(x_user, x_item, src_u, dst_i);
    }

    // idx3 (profiler capture slot): layer-1 dual GEMM -> h (bf16 hi/lo)
    {
        GP P;
        P.M[0] = N_USER;            P.M[1] = N_ITEM;
        P.Af[0] = a1u;              P.Af[1] = a1i;
        P.Ah[0] = xhi;              P.Ah[1] = xhi + XU_ELEMS;
        P.Al[0] = xlo;              P.Al[1] = xlo + XU_ELEMS;
        P.W1h[0] = whi + 2 * 32768; P.W1h[1] = whi + 0 * 32768;
        P.W1l[0] = wlo + 2 * 32768; P.W1l[1] = wlo + 0 * 32768;
        P.W2h[0] = whi + 3 * 32768; P.W2h[1] = whi + 1 * 32768;
        P.W2l[0] = wlo + 3 * 32768; P.W2l[1] = wlo + 1 * 32768;
        P.bias[0] = b1_iu;          P.bias[1] = b1_ui;
        P.deg[0] = deg_u;           P.deg[1] = deg_i;
        P.Cin[0] = nullptr;         P.Cin[1] = nullptr;
        P.Cf[0] = nullptr;          P.Cf[1] = nullptr;
        P.Ch[0] = hhi;              P.Ch[1] = hhi + H_OFF_I;
        P.Cl[0] = hlo;              P.Cl[1] = hlo + H_OFF_I;
        gemm_pair3<128, 256, true, true, false, true, true>
            <<<dim3(2, MT_U, 2), 256>>>(P);
    }

    // idx4: p = h @ Wl2 dual GEMM (fp32 out into reused agg buffers)
    {
        GP P;
        P.M[0] = N_USER;            P.M[1] = N_ITEM;
        P.Af[0] = nullptr;          P.Af[1] = nullptr;
        P.Ah[0] = hhi;              P.Ah[1] = hhi + H_OFF_I;
        P.Al[0] = hlo;              P.Al[1] = hlo + H_OFF_I;
        P.W1h[0] = whi + 4 * 32768; P.W1h[1] = whi + 6 * 32768;
        P.W1l[0] = wlo + 4 * 32768; P.W1l[1] = wlo + 6 * 32768;
        P.W2h[0] = nullptr;         P.W2h[1] = nullptr;
        P.W2l[0] = nullptr;         P.W2l[1] = nullptr;
        P.bias[0] = nullptr;        P.bias[1] = nullptr;
        P.deg[0] = nullptr;         P.deg[1] = nullptr;
        P.Cin[0] = nullptr;         P.Cin[1] = nullptr;
        P.Cf[0] = a1u;              P.Cf[1] = a1i;
        P.Ch[0] = nullptr;          P.Ch[1] = nullptr;
        P.Cl[0] = nullptr;          P.Cl[1] = nullptr;
        gemm_pair3<256, 128, false, false, false, false, false>
            <<<dim3(1, MT_U, 2), 256>>>(P);
    }

    // idx5: layer-2 scatter of transformed features
    {
        long long threads = (long long)NE * 32;
        scatter_p<<<(int)((threads + 255) / 256), 256>>>(src_u, dst_i);
    }

    // idx6: z = acc2/deg + h @ Wr2 + b2 dual GEMM
    {
        GP P;
        P.M[0] = N_USER;            P.M[1] = N_ITEM;
        P.Af[0] = nullptr;          P.Af[1] = nullptr;
        P.Ah[0] = hhi;              P.Ah[1] = hhi + H_OFF_I;
        P.Al[0] = hlo;              P.Al[1] = hlo + H_OFF_I;
        P.W1h[0] = whi + 7 * 32768; P.W1h[1] = whi + 5 * 32768;
        P.W1l[0] = wlo + 7 * 32768; P.W1l[1] = wlo + 5 * 32768;
        P.W2h[0] = nullptr;         P.W2h[1] = nullptr;
        P.W2l[0] = nullptr;         P.W2l[1] = nullptr;
        P.bias[0] = b2_iu;          P.bias[1] = b2_ui;
        P.deg[0] = deg_u;           P.deg[1] = deg_i;
        P.Cin[0] = c2u;             P.Cin[1] = c2i;
        P.Cf[0] = zu;               P.Cf[1] = zi;
        P.Ch[0] = nullptr;          P.Ch[1] = nullptr;
        P.Cl[0] = nullptr;          P.Cl[1] = nullptr;
        gemm_pair3<256, 128, false, true, true, false, false>
            <<<dim3(1, MT_U, 2), 256>>>(P);
    }

    // idx7: decode
    {
        long long threads = (long long)NL * 32;
        decode_kernel<<<(int)((threads + 255) / 256), 256>>>(label_src, label_dst, (float*)d_out);
    }
}

// round 10
// speedup vs baseline: 1.0521x; 1.0521x over previous
#include <cuda_runtime.h>
#include <cuda_bf16.h>
#include <cstdint>
#include <cstddef>

#define N_USER 50000
#define N_ITEM 20000
#define D_IN   128
#define D_HID  256
#define D_OUT  128
#define NE     300000
#define NL     200000

#define XU_ELEMS (N_USER * D_IN)
#define X_ELEMS  ((N_USER + N_ITEM) * D_IN)

// ---------------- device scratch (static, allocation-free) ----------------
__device__ float g_deg_user[N_USER];
__device__ float g_deg_item[N_ITEM];
__device__ float g_agg1_item[N_ITEM * D_IN];   // later reused as p_item
__device__ float g_agg1_user[N_USER * D_IN];   // later reused as p_user
__device__ float g_h_item[N_ITEM * D_HID];
__device__ float g_h_user[N_USER * D_HID];
__device__ float g_acc2_item[N_ITEM * D_OUT];
__device__ float g_acc2_user[N_USER * D_OUT];
__device__ float g_z_item[N_ITEM * D_OUT];
__device__ float g_z_user[N_USER * D_OUT];
// W pre-packed into smem fragment-tuple layout (bf16x2 words, hi/lo)
__device__ uint32_t g_pwh[8 * 16384];
__device__ uint32_t g_pwl[8 * 16384];
// x pre-split to bf16 hi/lo
__device__ __nv_bfloat16 g_xhi[X_ELEMS];
__device__ __nv_bfloat16 g_xlo[X_ELEMS];

// ---------------- helpers ----------------
__device__ __forceinline__ void split2(float x0, float x1, uint32_t& hi, uint32_t& lo) {
    __nv_bfloat162 h = __floats2bfloat162_rn(x0, x1);
    float r0 = x0 - __bfloat162float(__low2bfloat16(h));
    float r1 = x1 - __bfloat162float(__high2bfloat16(h));
    __nv_bfloat162 l = __floats2bfloat162_rn(r0, r1);
    hi = *reinterpret_cast<uint32_t*>(&h);
    lo = *reinterpret_cast<uint32_t*>(&l);
}

// ---------------- fused zero fill ----------------
__global__ void zero_multi6(float4* p0, int n0, float4* p1, int n1,
                            float4* p2, int n2, float4* p3, int n3,
                            float4* p4, int n4, float4* p5, int n5) {
    int i = blockIdx.x * blockDim.x + threadIdx.x;
    float4 z = make_float4(0.f, 0.f, 0.f, 0.f);
    if (i < n0) p0[i] = z;
    if (i < n1) p1[i] = z;
    if (i < n2) p2[i] = z;
    if (i < n3) p3[i] = z;
    if (i < n4) p4[i] = z;
    if (i < n5) p5[i] = z;
}

// ---------------- pack W into frag-tuple layout + split x (one launch) ------
// Packed layout per matrix (16384 words): widx = ((nblk*TPS + chunk) << 10) + t
//   t = pair*512 + wnb*128 + fg*16 + ft*4 + j
//   nt = 2*pair + (j>>1), b = j&1
//   n  = nblk*128 + wnb*32 + 8*nt + fg
//   k  = chunk*16 + 2*ft + 8*b       -> word packs (W[k][n], W[k+1][n])
#define PACK_WORK (8 * 16384)
#define X_WORK (X_ELEMS / 4)
__global__ void pack_split(const float* w0, const float* w1, const float* w2,
                           const float* w3, const float* w4, const float* w5,
                           const float* w6, const float* w7,
                           const float* xu, const float* xi) {
    int i = blockIdx.x * blockDim.x + threadIdx.x;
    if (i < PACK_WORK) {
        int w = i >> 14;
        int widx = i & 16383;
        const float* src;
        int Kdim, Ndim, TPS;
        switch (w) {
            case 0: src = w0; break;
            case 1: src = w1; break;
            case 2: src = w2; break;
            case 3: src = w3; break;
            case 4: src = w4; break;
            case 5: src = w5; break;
            case 6: src = w6; break;
            default: src = w7; break;
        }
        if (w < 4) { Kdim = 128; Ndim = 256; TPS = 8; }
        else       { Kdim = 256; Ndim = 128; TPS = 16; }
        (void)Kdim;
        int cb = widx >> 10;              // nblk*TPS + chunk
        int nblk = cb / TPS;
        int chunk = cb % TPS;
        int t = widx & 1023;
        int pair = t >> 9;
        int wnb = (t >> 7) & 3;
        int fg = (t >> 4) & 7;
        int ft = (t >> 2) & 3;
        int j = t & 3;
        int nt = 2 * pair + (j >> 1);
        int b = j & 1;
        int n = nblk * 128 + wnb * 32 + 8 * nt + fg;
        int k = chunk * 16 + 2 * ft + 8 * b;
        float v0 = src[k * Ndim + n];
        float v1 = src[(k + 1) * Ndim + n];
        uint32_t hw, lw;
        split2(v0, v1, hw, lw);
        g_pwh[i] = hw;
        g_pwl[i] = lw;
    } else {
        int j = i - PACK_WORK;
        if (j < X_WORK) {
            int f = j * 4;
            const float* src = (f < XU_ELEMS) ? (xu + f) : (xi + (f - XU_ELEMS));
            float4 v = *(const float4*)src;
            uint32_t h0, l0, h1, l1;
            split2(v.x, v.y, h0, l0);
            split2(v.z, v.w, h1, l1);
            ((uint2*)g_xhi)[j] = make_uint2(h0, h1);
            ((uint2*)g_xlo)[j] = make_uint2(l0, l1);
        }
    }
}

// ---------------- vectorized global reduction ----------------
__device__ __forceinline__ void red_add_v4(float* p, float4 v) {
    asm volatile("red.global.add.v4.f32 [%0], {%1, %2, %3, %4};"
                 :: "l"(p), "f"(v.x), "f"(v.y), "f"(v.z), "f"(v.w)
                 : "memory");
}

// ---------------- layer-1 edge scatter (128-dim) + degree count ----------------
__global__ void scatter_l1(const float* __restrict__ x_user,
                           const float* __restrict__ x_item,
                           const int* __restrict__ src,
                           const int* __restrict__ dst) {
    int gt = blockIdx.x * blockDim.x + threadIdx.x;
    int e = gt >> 5;
    int lane = gt & 31;
    if (e >= NE) return;
    int s = __ldg(src + e);
    int d = __ldg(dst + e);

    float4 vu = __ldg(&((const float4*)x_user)[s * 32 + lane]);
    red_add_v4(g_agg1_item + d * 128 + lane * 4, vu);

    float4 vi = __ldg(&((const float4*)x_item)[d * 32 + lane]);
    red_add_v4(g_agg1_user + s * 128 + lane * 4, vi);

    if (lane == 0) {
        atomicAdd(&g_deg_item[d], 1.f);
        atomicAdd(&g_deg_user[s], 1.f);
    }
}

// ---------------- layer-2 scatter of transformed features (128-dim) ----------------
__global__ void scatter_p(const int* __restrict__ src,
                          const int* __restrict__ dst) {
    int gt = blockIdx.x * blockDim.x + threadIdx.x;
    int e = gt >> 5;
    int lane = gt & 31;
    if (e >= NE) return;
    int s = __ldg(src + e);
    int d = __ldg(dst + e);

    float4 pu = __ldg(&((const float4*)g_agg1_user)[s * 32 + lane]);
    red_add_v4(g_acc2_item + d * 128 + lane * 4, pu);

    float4 pi = __ldg(&((const float4*)g_agg1_item)[d * 32 + lane]);
    red_add_v4(g_acc2_user + s * 128 + lane * 4, pi);
}

// ================= 3xBF16 mma.sync GEMM: frag-major A + pre-packed B ========
__device__ __forceinline__ void mma_bf16(float c[4],
                                         const uint32_t a[4],
                                         const uint32_t b[2]) {
    asm volatile(
        "mma.sync.aligned.m16n8k16.row.col.f32.bf16.bf16.f32 "
        "{%0,%1,%2,%3}, {%4,%5,%6,%7}, {%8,%9}, {%0,%1,%2,%3};"
        : "+f"(c[0]), "+f"(c[1]), "+f"(c[2]), "+f"(c[3])
        : "r"(a[0]), "r"(a[1]), "r"(a[2]), "r"(a[3]), "r"(b[0]), "r"(b[1]));
}

struct GP {
    int M[2];
    const float* Af[2];                 // fp32 A (seg0 scaled-agg, or single seg)
    const __nv_bfloat16* Ah[2];         // pre-split A (layer-1 seg1 = x)
    const __nv_bfloat16* Al[2];
    const uint32_t* PW1h[2];            // pre-packed W, frag-tuple layout
    const uint32_t* PW1l[2];
    const uint32_t* PW2h[2];
    const uint32_t* PW2l[2];
    const float* bias[2];
    const float* deg[2];
    const float* Cin[2];
    float* Cf[2];
};

template <int K, int N, bool SEG2, bool HASBIAS, bool CACC, bool RELU>
__global__ __launch_bounds__(256, 2)
void gemm_pp(GP P) {
    const int side = blockIdx.z;
    const int M = P.M[side];
    const int bm = blockIdx.y * 128;
    if (bm >= M) return;
    const int bn = blockIdx.x * 128;

    const float* __restrict__ Af = P.Af[side];
    const __nv_bfloat16* __restrict__ Ahp = P.Ah[side];
    const __nv_bfloat16* __restrict__ Alp = P.Al[side];
    const uint32_t* __restrict__ PW1h = P.PW1h[side];
    const uint32_t* __restrict__ PW1l = P.PW1l[side];
    const uint32_t* __restrict__ PW2h = P.PW2h[side];
    const uint32_t* __restrict__ PW2l = P.PW2l[side];
    const float* __restrict__ bias = P.bias[side];
    const float* __restrict__ deg = P.deg[side];
    const float* __restrict__ Cin = P.Cin[side];
    float* __restrict__ Cout = P.Cf[side];

    // A frag tuples: [wmblk 2][mt 4][fg 8][ft' 4][4 words] (R6 layout)
    __shared__ uint32_t AsH[2][1024];
    __shared__ uint32_t AsL[2][1024];
    // B frag tuples: pre-packed, linear
    __shared__ uint32_t BsH[2][1024];
    __shared__ uint32_t BsL[2][1024];

    const int tid = threadIdx.x;
    const int lane = tid & 31;
    const int w = tid >> 5;
    const int wmblk = w & 1;
    const int wm = wmblk * 64;
    const int wnb = w >> 1;
    const int wn = wnb * 32;
    const int fg = lane >> 2;
    const int ft = lane & 3;
    const int ftp = ft ^ ((fg >> 1) & 3);

    // ---- producer mappings (A: R6) ----
    const int arow = tid >> 1;
    const int khalf = tid & 1;
    const int am = bm + arow;
    const bool avalid = am < M;
    const int pwm = arow >> 6;
    const int pmt = (arow >> 4) & 3;
    const int pfg = arow & 7;
    const int prh = (arow >> 3) & 1;
    const int psw = (pfg >> 1) & 3;
    const int atbase = ((pwm * 4 + pmt) * 8 + pfg) * 16 + prh * 2 + khalf;
    // consumer A tuple base
    const int aidx = ((wmblk * 4) * 8 + fg) * 16;
    // consumer B tuple bases (linear frag-tuple layout, conflict-free)
    const int bidx0 = wnb * 128 + fg * 16 + ft * 4;
    const int bidx1 = 512 + bidx0;

    float ascale = 1.f;
    if (SEG2) ascale = avalid ? (1.f / fmaxf(__ldg(deg + am), 1.f)) : 0.f;

    float acc[4][4][4];
#pragma unroll
    for (int i = 0; i < 4; i++)
#pragma unroll
        for (int j = 0; j < 4; j++)
#pragma unroll
            for (int r = 0; r < 4; r++) acc[i][j][r] = 0.f;

    const int TPS = K / 16;
    const int NT = (SEG2 ? 2 : 1) * TPS;
    const int nblk = blockIdx.x;

    auto ldg_tile = [&](int t, bool& pres, float4& a0, float4& a1,
                        uint4& ah4, uint4& al4, uint4& bh4, uint4& bl4) {
        const bool seg1 = SEG2 && (t >= TPS);
        pres = seg1;                     // pre-split A only on layer-1 seg1
        const int chunk = seg1 ? (t - TPS) : t;
        const int k0 = chunk * 16;
        if (SEG2 && seg1) {
            ah4 = make_uint4(0u, 0u, 0u, 0u);
            al4 = ah4;
            if (avalid) {
                ah4 = *(const uint4*)(Ahp + (size_t)am * K + k0 + khalf * 8);
                al4 = *(const uint4*)(Alp + (size_t)am * K + k0 + khalf * 8);
            }
        } else {
            a0 = make_float4(0.f, 0.f, 0.f, 0.f);
            a1 = a0;
            if (avalid) {
                const float* ap = Af + (size_t)am * K + k0 + khalf * 8;
                a0 = *(const float4*)ap;
                a1 = *(const float4*)(ap + 4);
                if (SEG2) {
                    a0.x *= ascale; a0.y *= ascale; a0.z *= ascale; a0.w *= ascale;
                    a1.x *= ascale; a1.y *= ascale; a1.z *= ascale; a1.w *= ascale;
                }
            }
        }
        const uint32_t* Ph = seg1 ? PW2h : PW1h;
        const uint32_t* Pl = seg1 ? PW2l : PW1l;
        const int off = ((nblk * TPS + chunk) << 10) + (tid << 2);
        bh4 = *(const uint4*)(Ph + off);
        bl4 = *(const uint4*)(Pl + off);
    };

    auto sts_tile = [&](int s, bool pres, float4 a0, float4 a1,
                        uint4 ah4, uint4 al4, uint4 bh4, uint4 bl4) {
        uint32_t hw[4], lw[4];
        if (pres) {
            hw[0] = ah4.x; hw[1] = ah4.y; hw[2] = ah4.z; hw[3] = ah4.w;
            lw[0] = al4.x; lw[1] = al4.y; lw[2] = al4.z; lw[3] = al4.w;
        } else {
            float f[8] = {a0.x, a0.y, a0.z, a0.w, a1.x, a1.y, a1.z, a1.w};
#pragma unroll
            for (int j = 0; j < 4; j++) split2(f[2 * j], f[2 * j + 1], hw[j], lw[j]);
        }
#pragma unroll
        for (int j = 0; j < 4; j++) {
            int widx = atbase + (j ^ psw) * 4;
            AsH[s][widx] = hw[j];
            AsL[s][widx] = lw[j];
        }
        // B: pre-packed, linear store (bank-perfect)
        *(uint4*)&BsH[s][tid << 2] = bh4;
        *(uint4*)&BsL[s][tid << 2] = bl4;
    };

    {
        bool pres; float4 a0, a1; uint4 ah4, al4, bh4, bl4;
        ldg_tile(0, pres, a0, a1, ah4, al4, bh4, bl4);
        sts_tile(0, pres, a0, a1, ah4, al4, bh4, bl4);
    }
    __syncthreads();

    int buf = 0;
    for (int t = 0; t < NT; t++) {
        const bool more = (t + 1) < NT;
        bool npres; float4 na0, na1; uint4 nah4, nal4, nbh4, nbl4;
        if (more) ldg_tile(t + 1, npres, na0, na1, nah4, nal4, nbh4, nbl4);

        // ---- A-hi frags: 4 x LDS.128 ----
        uint32_t ah[4][4];
#pragma unroll
        for (int mt = 0; mt < 4; mt++) {
            uint4 v = *(const uint4*)&AsH[buf][aidx + mt * 128 + ftp * 4];
            ah[mt][0] = v.x; ah[mt][1] = v.z; ah[mt][2] = v.y; ah[mt][3] = v.w;
        }
        // ---- B-hi frags: 2 x LDS.128 ----
        uint32_t bh[4][2];
        {
            uint4 t0 = *(const uint4*)&BsH[buf][bidx0];
            uint4 t1 = *(const uint4*)&BsH[buf][bidx1];
            bh[0][0] = t0.x; bh[0][1] = t0.y; bh[1][0] = t0.z; bh[1][1] = t0.w;
            bh[2][0] = t1.x; bh[2][1] = t1.y; bh[3][0] = t1.z; bh[3][1] = t1.w;
        }
        // pass 1: Ah * Bh
#pragma unroll
        for (int mt = 0; mt < 4; mt++)
#pragma unroll
            for (int nt = 0; nt < 4; nt++) mma_bf16(acc[mt][nt], ah[mt], bh[nt]);

        // pass 2: Ah * Bl
        {
            uint32_t bl[4][2];
            uint4 t0 = *(const uint4*)&BsL[buf][bidx0];
            uint4 t1 = *(const uint4*)&BsL[buf][bidx1];
            bl[0][0] = t0.x; bl[0][1] = t0.y; bl[1][0] = t0.z; bl[1][1] = t0.w;
            bl[2][0] = t1.x; bl[2][1] = t1.y; bl[3][0] = t1.z; bl[3][1] = t1.w;
#pragma unroll
            for (int mt = 0; mt < 4; mt++)
#pragma unroll
                for (int nt = 0; nt < 4; nt++) mma_bf16(acc[mt][nt], ah[mt], bl[nt]);
        }

        // pass 3: Al * Bh
        {
            uint32_t al[4][4];
#pragma unroll
            for (int mt = 0; mt < 4; mt++) {
                uint4 v = *(const uint4*)&AsL[buf][aidx + mt * 128 + ftp * 4];
                al[mt][0] = v.x; al[mt][1] = v.z; al[mt][2] = v.y; al[mt][3] = v.w;
            }
#pragma unroll
            for (int mt = 0; mt < 4; mt++)
#pragma unroll
                for (int nt = 0; nt < 4; nt++) mma_bf16(acc[mt][nt], al[mt], bh[nt]);
        }

        if (more) {
            sts_tile(buf ^ 1, npres, na0, na1, nah4, nal4, nbh4, nbl4);
            __syncthreads();
            buf ^= 1;
        }
    }

    // ---------------- epilogue (R6: fp32 float2 stores) ----------------
#pragma unroll
    for (int nt = 0; nt < 4; nt++) {
        const int c0 = bn + wn + 8 * nt + 2 * ft;
        float b0 = 0.f, b1 = 0.f;
        if (HASBIAS) {
            b0 = __ldg(bias + c0);
            b1 = __ldg(bias + c0 + 1);
        }
#pragma unroll
        for (int mt = 0; mt < 4; mt++) {
            const int r0 = bm + wm + 16 * mt + fg;
            const int r1 = r0 + 8;
            float o00 = acc[mt][nt][0] + b0;
            float o01 = acc[mt][nt][1] + b1;
            float o10 = acc[mt][nt][2] + b0;
            float o11 = acc[mt][nt][3] + b1;
            if (CACC) {
                if (r0 < M) {
                    float id0 = 1.f / fmaxf(__ldg(deg + r0), 1.f);
                    float2 ci = *(const float2*)(Cin + (size_t)r0 * N + c0);
                    o00 += ci.x * id0;
                    o01 += ci.y * id0;
                }
                if (r1 < M) {
                    float id1 = 1.f / fmaxf(__ldg(deg + r1), 1.f);
                    float2 ci = *(const float2*)(Cin + (size_t)r1 * N + c0);
                    o10 += ci.x * id1;
                    o11 += ci.y * id1;
                }
            }
            if (RELU) {
                o00 = fmaxf(o00, 0.f); o01 = fmaxf(o01, 0.f);
                o10 = fmaxf(o10, 0.f); o11 = fmaxf(o11, 0.f);
            }
            if (r0 < M) *(float2*)(Cout + (size_t)r0 * N + c0) = make_float2(o00, o01);
            if (r1 < M) *(float2*)(Cout + (size_t)r1 * N + c0) = make_float2(o10, o11);
        }
    }
}

// ---------------- decode ----------------
__global__ void decode_kernel(const int* __restrict__ ls,
                              const int* __restrict__ ld,
                              float* __restrict__ out) {
    int gt = blockIdx.x * blockDim.x + threadIdx.x;
    int i = gt >> 5;
    int lane = gt & 31;
    if (i >= NL) return;
    int a = __ldg(ls + i);
    int b = __ldg(ld + i);
    float4 u = ((const float4*)g_z_user)[a * 32 + lane];
    float4 v = ((const float4*)g_z_item)[b * 32 + lane];
    float s = u.x * v.x + u.y * v.y + u.z * v.z + u.w * v.w;
#pragma unroll
    for (int o = 16; o > 0; o >>= 1) s += __shfl_down_sync(0xffffffffu, s, o);
    if (lane == 0) {
        out[i] = -s;
        out[NL + i] = s;
    }
}

// ---------------- host launch ----------------
extern "C" void kernel_launch(void* const* d_in, const int* in_sizes, int n_in,
                              void* d_out, int out_size) {
    const float* x_user = (const float*)d_in[0];
    const float* x_item = (const float*)d_in[1];
    const float* Wl1_ui = (const float*)d_in[2];
    const float* Wr1_ui = (const float*)d_in[3];
    const float* b1_ui  = (const float*)d_in[4];
    const float* Wl1_iu = (const float*)d_in[5];
    const float* Wr1_iu = (const float*)d_in[6];
    const float* b1_iu  = (const float*)d_in[7];
    const float* Wl2_ui = (const float*)d_in[8];
    const float* Wr2_ui = (const float*)d_in[9];
    const float* b2_ui  = (const float*)d_in[10];
    const float* Wl2_iu = (const float*)d_in[11];
    const float* Wr2_iu = (const float*)d_in[12];
    const float* b2_iu  = (const float*)d_in[13];
    const int* src_u     = (const int*)d_in[14];
    const int* dst_i     = (const int*)d_in[15];
    const int* label_src = (const int*)d_in[16];
    const int* label_dst = (const int*)d_in[17];

    float *deg_u, *deg_i, *a1i, *a1u, *hi, *hu, *c2i, *c2u, *zi, *zu;
    uint32_t *pwh, *pwl;
    __nv_bfloat16 *xhi, *xlo;
    cudaGetSymbolAddress((void**)&deg_u, g_deg_user);
    cudaGetSymbolAddress((void**)&deg_i, g_deg_item);
    cudaGetSymbolAddress((void**)&a1i, g_agg1_item);
    cudaGetSymbolAddress((void**)&a1u, g_agg1_user);
    cudaGetSymbolAddress((void**)&hi, g_h_item);
    cudaGetSymbolAddress((void**)&hu, g_h_user);
    cudaGetSymbolAddress((void**)&c2i, g_acc2_item);
    cudaGetSymbolAddress((void**)&c2u, g_acc2_user);
    cudaGetSymbolAddress((void**)&zi, g_z_item);
    cudaGetSymbolAddress((void**)&zu, g_z_user);
    cudaGetSymbolAddress((void**)&pwh, g_pwh);
    cudaGetSymbolAddress((void**)&pwl, g_pwl);
    cudaGetSymbolAddress((void**)&xhi, g_xhi);
    cudaGetSymbolAddress((void**)&xlo, g_xlo);

    const int MT_U = (N_USER + 127) / 128;   // 391

    // idx0: zero accumulators + degree counters
    {
        int n0 = N_ITEM * D_IN / 4, n1 = N_USER * D_IN / 4;
        int n2 = N_USER / 4, n3 = N_ITEM / 4;
        int n4 = N_ITEM * D_OUT / 4, n5 = N_USER * D_OUT / 4;
        zero_multi6<<<(n1 + 255) / 256, 256>>>((float4*)a1i, n0, (float4*)a1u, n1,
                                               (float4*)deg_u, n2, (float4*)deg_i, n3,
                                               (float4*)c2i, n4, (float4*)c2u, n5);
    }

    // idx1: pack weights (frag-tuple layout) + split x
    {
        int total = PACK_WORK + X_WORK;
        pack_split<<<(total + 255) / 256, 256>>>(Wl1_ui, Wr1_ui, Wl1_iu, Wr1_iu,
                                                 Wl2_ui, Wr2_ui, Wl2_iu, Wr2_iu,
                                                 x_user, x_item);
    }

    // idx2: layer-1 scatter + degrees
    {
        long long threads = (long long)NE * 32;
        scatter_l1<<<(int)((threads + 255) / 256), 256>>>(x_user, x_item, src_u, dst_i);
    }

    // idx3 (profiler capture slot): layer-1 dual GEMM -> h (fp32)
    {
        GP P;
        P.M[0] = N_USER;              P.M[1] = N_ITEM;
        P.Af[0] = a1u;                P.Af[1] = a1i;
        P.Ah[0] = xhi;                P.Ah[1] = xhi + XU_ELEMS;
        P.Al[0] = xlo;                P.Al[1] = xlo + XU_ELEMS;
        P.PW1h[0] = pwh + 2 * 16384;  P.PW1h[1] = pwh + 0 * 16384;
        P.PW1l[0] = pwl + 2 * 16384;  P.PW1l[1] = pwl + 0 * 16384;
        P.PW2h[0] = pwh + 3 * 16384;  P.PW2h[1] = pwh + 1 * 16384;
        P.PW2l[0] = pwl + 3 * 16384;  P.PW2l[1] = pwl + 1 * 16384;
        P.bias[0] = b1_iu;            P.bias[1] = b1_ui;
        P.deg[0] = deg_u;             P.deg[1] = deg_i;
        P.Cin[0] = nullptr;           P.Cin[1] = nullptr;
        P.Cf[0] = hu;                 P.Cf[1] = hi;
        gemm_pp<128, 256, true, true, false, true>
            <<<dim3(2, MT_U, 2), 256>>>(P);
    }

    // idx4: p = h @ Wl2 dual GEMM (fp32 out into reused agg buffers)
    {
        GP P;
        P.M[0] = N_USER;              P.M[1] = N_ITEM;
        P.Af[0] = hu;                 P.Af[1] = hi;
        P.Ah[0] = nullptr;            P.Ah[1] = nullptr;
        P.Al[0] = nullptr;            P.Al[1] = nullptr;
        P.PW1h[0] = pwh + 4 * 16384;  P.PW1h[1] = pwh + 6 * 16384;
        P.PW1l[0] = pwl + 4 * 16384;  P.PW1l[1] = pwl + 6 * 16384;
        P.PW2h[0] = nullptr;          P.PW2h[1] = nullptr;
        P.PW2l[0] = nullptr;          P.PW2l[1] = nullptr;
        P.bias[0] = nullptr;          P.bias[1] = nullptr;
        P.deg[0] = nullptr;           P.deg[1] = nullptr;
        P.Cin[0] = nullptr;           P.Cin[1] = nullptr;
        P.Cf[0] = a1u;                P.Cf[1] = a1i;
        gemm_pp<256, 128, false, false, false, false>
            <<<dim3(1, MT_U, 2), 256>>>(P);
    }

    // idx5: layer-2 scatter of transformed features
    {
        long long threads = (long long)NE * 32;
        scatter_p<<<(int)((threads + 255) / 256), 256>>>(src_u, dst_i);
    }

    // idx6: z = acc2/deg + h @ Wr2 + b2 dual GEMM
    {
        GP P;
        P.M[0] = N_USER;              P.M[1] = N_ITEM;
        P.Af[0] = hu;                 P.Af[1] = hi;
        P.Ah[0] = nullptr;            P.Ah[1] = nullptr;
        P.Al[0] = nullptr;            P.Al[1] = nullptr;
        P.PW1h[0] = pwh + 7 * 16384;  P.PW1h[1] = pwh + 5 * 16384;
        P.PW1l[0] = pwl + 7 * 16384;  P.PW1l[1] = pwl + 5 * 16384;
        P.PW2h[0] = nullptr;          P.PW2h[1] = nullptr;
        P.PW2l[0] = nullptr;          P.PW2l[1] = nullptr;
        P.bias[0] = b2_iu;            P.bias[1] = b2_ui;
        P.deg[0] = deg_u;             P.deg[1] = deg_i;
        P.Cin[0] = c2u;               P.Cin[1] = c2i;
        P.Cf[0] = zu;                 P.Cf[1] = zi;
        gemm_pp<256, 128, false, true, true, false>
            <<<dim3(1, MT_U, 2), 256>>>(P);
    }

    // idx7: decode
    {
        long long threads = (long long)NL * 32;
        decode_kernel<<<(int)((threads + 255) / 256), 256>>>(label_src, label_dst, (float*)d_out);
    }
}

// round 11
// speedup vs baseline: 1.0808x; 1.0273x over previous
#include <cuda_runtime.h>
#include <cuda_bf16.h>
#include <cstdint>
#include <cstddef>

#define N_USER 50000
#define N_ITEM 20000
#define D_IN   128
#define D_HID  256
#define D_OUT  128
#define NE     300000
#define NL     200000

// ---------------- device scratch (static, allocation-free) ----------------
__device__ float g_deg_user[N_USER];
__device__ float g_deg_item[N_ITEM];
__device__ float g_agg1_item[N_ITEM * D_IN];   // later reused as p_item
__device__ float g_agg1_user[N_USER * D_IN];   // later reused as p_user
__device__ float g_h_item[N_ITEM * D_HID];
__device__ float g_h_user[N_USER * D_HID];
__device__ float g_acc2_item[N_ITEM * D_OUT];
__device__ float g_acc2_user[N_USER * D_OUT];
__device__ float g_z_item[N_ITEM * D_OUT];
__device__ float g_z_user[N_USER * D_OUT];
// W pre-packed into smem fragment-tuple layout (bf16x2 words, hi/lo)
__device__ uint32_t g_pwh[8 * 16384];
__device__ uint32_t g_pwl[8 * 16384];

// ---------------- helpers ----------------
__device__ __forceinline__ void split2(float x0, float x1, uint32_t& hi, uint32_t& lo) {
    __nv_bfloat162 h = __floats2bfloat162_rn(x0, x1);
    float r0 = x0 - __bfloat162float(__low2bfloat16(h));
    float r1 = x1 - __bfloat162float(__high2bfloat16(h));
    __nv_bfloat162 l = __floats2bfloat162_rn(r0, r1);
    hi = *reinterpret_cast<uint32_t*>(&h);
    lo = *reinterpret_cast<uint32_t*>(&l);
}

// ---------------- fused zero fill ----------------
__global__ void zero_multi6(float4* p0, int n0, float4* p1, int n1,
                            float4* p2, int n2, float4* p3, int n3,
                            float4* p4, int n4, float4* p5, int n5) {
    int i = blockIdx.x * blockDim.x + threadIdx.x;
    float4 z = make_float4(0.f, 0.f, 0.f, 0.f);
    if (i < n0) p0[i] = z;
    if (i < n1) p1[i] = z;
    if (i < n2) p2[i] = z;
    if (i < n3) p3[i] = z;
    if (i < n4) p4[i] = z;
    if (i < n5) p5[i] = z;
}

// ---------------- pack W into frag-tuple layout (one launch) ------
// Packed layout per matrix (16384 words): widx = ((nblk*TPS + chunk) << 10) + t
//   t = pair*512 + wnb*128 + fg*16 + ft*4 + j
//   nt = 2*pair + (j>>1), b = j&1
//   n  = nblk*128 + wnb*32 + 8*nt + fg
//   k  = chunk*16 + 2*ft + 8*b       -> word packs (W[k][n], W[k+1][n])
#define PACK_WORK (8 * 16384)
__global__ void pack_w(const float* w0, const float* w1, const float* w2,
                       const float* w3, const float* w4, const float* w5,
                       const float* w6, const float* w7) {
    int i = blockIdx.x * blockDim.x + threadIdx.x;
    if (i >= PACK_WORK) return;
    int w = i >> 14;
    int widx = i & 16383;
    const float* src;
    int Ndim, TPS;
    switch (w) {
        case 0: src = w0; break;
        case 1: src = w1; break;
        case 2: src = w2; break;
        case 3: src = w3; break;
        case 4: src = w4; break;
        case 5: src = w5; break;
        case 6: src = w6; break;
        default: src = w7; break;
    }
    if (w < 4) { Ndim = 256; TPS = 8; }
    else       { Ndim = 128; TPS = 16; }
    int cb = widx >> 10;              // nblk*TPS + chunk
    int nblk = cb / TPS;
    int chunk = cb % TPS;
    int t = widx & 1023;
    int pair = t >> 9;
    int wnb = (t >> 7) & 3;
    int fg = (t >> 4) & 7;
    int ft = (t >> 2) & 3;
    int j = t & 3;
    int nt = 2 * pair + (j >> 1);
    int b = j & 1;
    int n = nblk * 128 + wnb * 32 + 8 * nt + fg;
    int k = chunk * 16 + 2 * ft + 8 * b;
    float v0 = __ldg(src + k * Ndim + n);
    float v1 = __ldg(src + (k + 1) * Ndim + n);
    uint32_t hw, lw;
    split2(v0, v1, hw, lw);
    g_pwh[i] = hw;
    g_pwl[i] = lw;
}

// ---------------- vectorized global reduction ----------------
__device__ __forceinline__ void red_add_v4(float* p, float4 v) {
    asm volatile("red.global.add.v4.f32 [%0], {%1, %2, %3, %4};"
                 :: "l"(p), "f"(v.x), "f"(v.y), "f"(v.z), "f"(v.w)
                 : "memory");
}

// ---------------- layer-1 edge scatter (128-dim) + degree count ----------------
__global__ void scatter_l1(const float* __restrict__ x_user,
                           const float* __restrict__ x_item,
                           const int* __restrict__ src,
                           const int* __restrict__ dst) {
    int gt = blockIdx.x * blockDim.x + threadIdx.x;
    int e = gt >> 5;
    int lane = gt & 31;
    if (e >= NE) return;
    int s = __ldg(src + e);
    int d = __ldg(dst + e);

    float4 vu = __ldg(&((const float4*)x_user)[s * 32 + lane]);
    red_add_v4(g_agg1_item + d * 128 + lane * 4, vu);

    float4 vi = __ldg(&((const float4*)x_item)[d * 32 + lane]);
    red_add_v4(g_agg1_user + s * 128 + lane * 4, vi);

    if (lane == 0) {
        atomicAdd(&g_deg_item[d], 1.f);
        atomicAdd(&g_deg_user[s], 1.f);
    }
}

// ---------------- layer-2 scatter of transformed features (128-dim) ----------------
__global__ void scatter_p(const int* __restrict__ src,
                          const int* __restrict__ dst) {
    int gt = blockIdx.x * blockDim.x + threadIdx.x;
    int e = gt >> 5;
    int lane = gt & 31;
    if (e >= NE) return;
    int s = __ldg(src + e);
    int d = __ldg(dst + e);

    float4 pu = __ldg(&((const float4*)g_agg1_user)[s * 32 + lane]);
    red_add_v4(g_acc2_item + d * 128 + lane * 4, pu);

    float4 pi = __ldg(&((const float4*)g_agg1_item)[d * 32 + lane]);
    red_add_v4(g_acc2_user + s * 128 + lane * 4, pi);
}

// ================= 3xBF16 mma.sync GEMM: frag-major A + pre-packed B ========
__device__ __forceinline__ void mma_bf16(float c[4],
                                         const uint32_t a[4],
                                         const uint32_t b[2]) {
    asm volatile(
        "mma.sync.aligned.m16n8k16.row.col.f32.bf16.bf16.f32 "
        "{%0,%1,%2,%3}, {%4,%5,%6,%7}, {%8,%9}, {%0,%1,%2,%3};"
        : "+f"(c[0]), "+f"(c[1]), "+f"(c[2]), "+f"(c[3])
        : "r"(a[0]), "r"(a[1]), "r"(a[2]), "r"(a[3]), "r"(b[0]), "r"(b[1]));
}

struct GP {
    int M[2];
    const float* A1[2];                 // fp32 A seg0 (scaled by 1/deg if SEG2)
    const float* A2[2];                 // fp32 A seg1 (SEG2 only)
    const uint32_t* PW1h[2];            // pre-packed W, frag-tuple layout
    const uint32_t* PW1l[2];
    const uint32_t* PW2h[2];
    const uint32_t* PW2l[2];
    const float* bias[2];
    const float* deg[2];
    const float* Cin[2];
    float* Cf[2];
};

template <int K, int N, bool SEG2, bool HASBIAS, bool CACC, bool RELU>
__global__ __launch_bounds__(256, 2)
void gemm_pp(GP P) {
    const int side = blockIdx.z;
    const int M = P.M[side];
    const int bm = blockIdx.y * 128;
    if (bm >= M) return;
    const int bn = blockIdx.x * 128;

    const float* __restrict__ A1 = P.A1[side];
    const float* __restrict__ A2 = P.A2[side];
    const uint32_t* __restrict__ PW1h = P.PW1h[side];
    const uint32_t* __restrict__ PW1l = P.PW1l[side];
    const uint32_t* __restrict__ PW2h = P.PW2h[side];
    const uint32_t* __restrict__ PW2l = P.PW2l[side];
    const float* __restrict__ bias = P.bias[side];
    const float* __restrict__ deg = P.deg[side];
    const float* __restrict__ Cin = P.Cin[side];
    float* __restrict__ Cout = P.Cf[side];

    // A frag tuples: [wmblk 2][mt 4][fg 8][ft' 4][4 words] (R6 layout)
    __shared__ uint32_t AsH[2][1024];
    __shared__ uint32_t AsL[2][1024];
    // B frag tuples: pre-packed, linear
    __shared__ uint32_t BsH[2][1024];
    __shared__ uint32_t BsL[2][1024];

    const int tid = threadIdx.x;
    const int lane = tid & 31;
    const int w = tid >> 5;
    const int wmblk = w & 1;
    const int wm = wmblk * 64;
    const int wnb = w >> 1;
    const int wn = wnb * 32;
    const int fg = lane >> 2;
    const int ft = lane & 3;
    const int ftp = ft ^ ((fg >> 1) & 3);

    // ---- producer mappings (A: R6) ----
    const int arow = tid >> 1;
    const int khalf = tid & 1;
    const int am = bm + arow;
    const bool avalid = am < M;
    const int pwm = arow >> 6;
    const int pmt = (arow >> 4) & 3;
    const int pfg = arow & 7;
    const int prh = (arow >> 3) & 1;
    const int psw = (pfg >> 1) & 3;
    const int atbase = ((pwm * 4 + pmt) * 8 + pfg) * 16 + prh * 2 + khalf;
    // consumer A tuple base
    const int aidx = ((wmblk * 4) * 8 + fg) * 16;
    // consumer B tuple bases (linear frag-tuple layout, conflict-free)
    const int bidx0 = wnb * 128 + fg * 16 + ft * 4;
    const int bidx1 = 512 + bidx0;

    float ascale = 1.f;
    if (SEG2) ascale = avalid ? (1.f / fmaxf(__ldg(deg + am), 1.f)) : 0.f;

    float acc[4][4][4];
#pragma unroll
    for (int i = 0; i < 4; i++)
#pragma unroll
        for (int j = 0; j < 4; j++)
#pragma unroll
            for (int r = 0; r < 4; r++) acc[i][j][r] = 0.f;

    const int TPS = K / 16;
    const int NT = (SEG2 ? 2 : 1) * TPS;
    const int nblk = blockIdx.x;

    auto ldg_tile = [&](int t, float4& a0, float4& a1, uint4& bh4, uint4& bl4) {
        const bool seg1 = SEG2 && (t >= TPS);
        const int chunk = seg1 ? (t - TPS) : t;
        const int k0 = chunk * 16;
        const float* A = seg1 ? A2 : A1;
        a0 = make_float4(0.f, 0.f, 0.f, 0.f);
        a1 = a0;
        if (avalid) {
            const float* ap = A + (size_t)am * K + k0 + khalf * 8;
            a0 = *(const float4*)ap;
            a1 = *(const float4*)(ap + 4);
            if (SEG2 && !seg1) {
                a0.x *= ascale; a0.y *= ascale; a0.z *= ascale; a0.w *= ascale;
                a1.x *= ascale; a1.y *= ascale; a1.z *= ascale; a1.w *= ascale;
            }
        }
        const uint32_t* Ph = seg1 ? PW2h : PW1h;
        const uint32_t* Pl = seg1 ? PW2l : PW1l;
        const int off = ((nblk * TPS + chunk) << 10) + (tid << 2);
        bh4 = *(const uint4*)(Ph + off);
        bl4 = *(const uint4*)(Pl + off);
    };

    auto sts_tile = [&](int s, float4 a0, float4 a1, uint4 bh4, uint4 bl4) {
        uint32_t hw[4], lw[4];
        float f[8] = {a0.x, a0.y, a0.z, a0.w, a1.x, a1.y, a1.z, a1.w};
#pragma unroll
        for (int j = 0; j < 4; j++) split2(f[2 * j], f[2 * j + 1], hw[j], lw[j]);
#pragma unroll
        for (int j = 0; j < 4; j++) {
            int widx = atbase + (j ^ psw) * 4;
            AsH[s][widx] = hw[j];
            AsL[s][widx] = lw[j];
        }
        // B: pre-packed, linear store (bank-perfect)
        *(uint4*)&BsH[s][tid << 2] = bh4;
        *(uint4*)&BsL[s][tid << 2] = bl4;
    };

    {
        float4 a0, a1; uint4 bh4, bl4;
        ldg_tile(0, a0, a1, bh4, bl4);
        sts_tile(0, a0, a1, bh4, bl4);
    }
    __syncthreads();

    int buf = 0;
    for (int t = 0; t < NT; t++) {
        const bool more = (t + 1) < NT;
        float4 na0, na1; uint4 nbh4, nbl4;
        if (more) ldg_tile(t + 1, na0, na1, nbh4, nbl4);

        // ---- A-hi frags: 4 x LDS.128 ----
        uint32_t ah[4][4];
#pragma unroll
        for (int mt = 0; mt < 4; mt++) {
            uint4 v = *(const uint4*)&AsH[buf][aidx + mt * 128 + ftp * 4];
            ah[mt][0] = v.x; ah[mt][1] = v.z; ah[mt][2] = v.y; ah[mt][3] = v.w;
        }
        // ---- B-hi frags: 2 x LDS.128 ----
        uint32_t bh[4][2];
        {
            uint4 t0 = *(const uint4*)&BsH[buf][bidx0];
            uint4 t1 = *(const uint4*)&BsH[buf][bidx1];
            bh[0][0] = t0.x; bh[0][1] = t0.y; bh[1][0] = t0.z; bh[1][1] = t0.w;
            bh[2][0] = t1.x; bh[2][1] = t1.y; bh[3][0] = t1.z; bh[3][1] = t1.w;
        }
        // pass 1: Ah * Bh
#pragma unroll
        for (int mt = 0; mt < 4; mt++)
#pragma unroll
            for (int nt = 0; nt < 4; nt++) mma_bf16(acc[mt][nt], ah[mt], bh[nt]);

        // pass 2: Ah * Bl
        {
            uint32_t bl[4][2];
            uint4 t0 = *(const uint4*)&BsL[buf][bidx0];
            uint4 t1 = *(const uint4*)&BsL[buf][bidx1];
            bl[0][0] = t0.x; bl[0][1] = t0.y; bl[1][0] = t0.z; bl[1][1] = t0.w;
            bl[2][0] = t1.x; bl[2][1] = t1.y; bl[3][0] = t1.z; bl[3][1] = t1.w;
#pragma unroll
            for (int mt = 0; mt < 4; mt++)
#pragma unroll
                for (int nt = 0; nt < 4; nt++) mma_bf16(acc[mt][nt], ah[mt], bl[nt]);
        }

        // pass 3: Al * Bh
        {
            uint32_t al[4][4];
#pragma unroll
            for (int mt = 0; mt < 4; mt++) {
                uint4 v = *(const uint4*)&AsL[buf][aidx + mt * 128 + ftp * 4];
                al[mt][0] = v.x; al[mt][1] = v.z; al[mt][2] = v.y; al[mt][3] = v.w;
            }
#pragma unroll
            for (int mt = 0; mt < 4; mt++)
#pragma unroll
                for (int nt = 0; nt < 4; nt++) mma_bf16(acc[mt][nt], al[mt], bh[nt]);
        }

        if (more) {
            sts_tile(buf ^ 1, na0, na1, nbh4, nbl4);
            __syncthreads();
            buf ^= 1;
        }
    }

    // ---------------- epilogue (fp32 float2 stores) ----------------
#pragma unroll
    for (int nt = 0; nt < 4; nt++) {
        const int c0 = bn + wn + 8 * nt + 2 * ft;
        float b0 = 0.f, b1 = 0.f;
        if (HASBIAS) {
            b0 = __ldg(bias + c0);
            b1 = __ldg(bias + c0 + 1);
        }
#pragma unroll
        for (int mt = 0; mt < 4; mt++) {
            const int r0 = bm + wm + 16 * mt + fg;
            const int r1 = r0 + 8;
            float o00 = acc[mt][nt][0] + b0;
            float o01 = acc[mt][nt][1] + b1;
            float o10 = acc[mt][nt][2] + b0;
            float o11 = acc[mt][nt][3] + b1;
            if (CACC) {
                if (r0 < M) {
                    float id0 = 1.f / fmaxf(__ldg(deg + r0), 1.f);
                    float2 ci = *(const float2*)(Cin + (size_t)r0 * N + c0);
                    o00 += ci.x * id0;
                    o01 += ci.y * id0;
                }
                if (r1 < M) {
                    float id1 = 1.f / fmaxf(__ldg(deg + r1), 1.f);
                    float2 ci = *(const float2*)(Cin + (size_t)r1 * N + c0);
                    o10 += ci.x * id1;
                    o11 += ci.y * id1;
                }
            }
            if (RELU) {
                o00 = fmaxf(o00, 0.f); o01 = fmaxf(o01, 0.f);
                o10 = fmaxf(o10, 0.f); o11 = fmaxf(o11, 0.f);
            }
            if (r0 < M) *(float2*)(Cout + (size_t)r0 * N + c0) = make_float2(o00, o01);
            if (r1 < M) *(float2*)(Cout + (size_t)r1 * N + c0) = make_float2(o10, o11);
        }
    }
}

// ---------------- decode ----------------
__global__ void decode_kernel(const int* __restrict__ ls,
                              const int* __restrict__ ld,
                              float* __restrict__ out) {
    int gt = blockIdx.x * blockDim.x + threadIdx.x;
    int i = gt >> 5;
    int lane = gt & 31;
    if (i >= NL) return;
    int a = __ldg(ls + i);
    int b = __ldg(ld + i);
    float4 u = ((const float4*)g_z_user)[a * 32 + lane];
    float4 v = ((const float4*)g_z_item)[b * 32 + lane];
    float s = u.x * v.x + u.y * v.y + u.z * v.z + u.w * v.w;
#pragma unroll
    for (int o = 16; o > 0; o >>= 1) s += __shfl_down_sync(0xffffffffu, s, o);
    if (lane == 0) {
        out[i] = -s;
        out[NL + i] = s;
    }
}

// ---------------- host launch ----------------
extern "C" void kernel_launch(void* const* d_in, const int* in_sizes, int n_in,
                              void* d_out, int out_size) {
    const float* x_user = (const float*)d_in[0];
    const float* x_item = (const float*)d_in[1];
    const float* Wl1_ui = (const float*)d_in[2];
    const float* Wr1_ui = (const float*)d_in[3];
    const float* b1_ui  = (const float*)d_in[4];
    const float* Wl1_iu = (const float*)d_in[5];
    const float* Wr1_iu = (const float*)d_in[6];
    const float* b1_iu  = (const float*)d_in[7];
    const float* Wl2_ui = (const float*)d_in[8];
    const float* Wr2_ui = (const float*)d_in[9];
    const float* b2_ui  = (const float*)d_in[10];
    const float* Wl2_iu = (const float*)d_in[11];
    const float* Wr2_iu = (const float*)d_in[12];
    const float* b2_iu  = (const float*)d_in[13];
    const int* src_u     = (const int*)d_in[14];
    const int* dst_i     = (const int*)d_in[15];
    const int* label_src = (const int*)d_in[16];
    const int* label_dst = (const int*)d_in[17];

    float *deg_u, *deg_i, *a1i, *a1u, *hi, *hu, *c2i, *c2u, *zi, *zu;
    uint32_t *pwh, *pwl;
    cudaGetSymbolAddress((void**)&deg_u, g_deg_user);
    cudaGetSymbolAddress((void**)&deg_i, g_deg_item);
    cudaGetSymbolAddress((void**)&a1i, g_agg1_item);
    cudaGetSymbolAddress((void**)&a1u, g_agg1_user);
    cudaGetSymbolAddress((void**)&hi, g_h_item);
    cudaGetSymbolAddress((void**)&hu, g_h_user);
    cudaGetSymbolAddress((void**)&c2i, g_acc2_item);
    cudaGetSymbolAddress((void**)&c2u, g_acc2_user);
    cudaGetSymbolAddress((void**)&zi, g_z_item);
    cudaGetSymbolAddress((void**)&zu, g_z_user);
    cudaGetSymbolAddress((void**)&pwh, g_pwh);
    cudaGetSymbolAddress((void**)&pwl, g_pwl);

    const int MT_U = (N_USER + 127) / 128;   // 391

    // idx0: zero accumulators + degree counters
    {
        int n0 = N_ITEM * D_IN / 4, n1 = N_USER * D_IN / 4;
        int n2 = N_USER / 4, n3 = N_ITEM / 4;
        int n4 = N_ITEM * D_OUT / 4, n5 = N_USER * D_OUT / 4;
        zero_multi6<<<(n1 + 255) / 256, 256>>>((float4*)a1i, n0, (float4*)a1u, n1,
                                               (float4*)deg_u, n2, (float4*)deg_i, n3,
                                               (float4*)c2i, n4, (float4*)c2u, n5);
    }

    // idx1: pack weights (frag-tuple layout) — W only, x stays fp32
    pack_w<<<(PACK_WORK + 255) / 256, 256>>>(Wl1_ui, Wr1_ui, Wl1_iu, Wr1_iu,
                                             Wl2_ui, Wr2_ui, Wl2_iu, Wr2_iu);

    // idx2: layer-1 scatter + degrees
    {
        long long threads = (long long)NE * 32;
        scatter_l1<<<(int)((threads + 255) / 256), 256>>>(x_user, x_item, src_u, dst_i);
    }

    // idx3 (profiler capture slot): layer-1 dual GEMM -> h (fp32)
    {
        GP P;
        P.M[0] = N_USER;              P.M[1] = N_ITEM;
        P.A1[0] = a1u;                P.A1[1] = a1i;
        P.A2[0] = x_user;             P.A2[1] = x_item;
        P.PW1h[0] = pwh + 2 * 16384;  P.PW1h[1] = pwh + 0 * 16384;
        P.PW1l[0] = pwl + 2 * 16384;  P.PW1l[1] = pwl + 0 * 16384;
        P.PW2h[0] = pwh + 3 * 16384;  P.PW2h[1] = pwh + 1 * 16384;
        P.PW2l[0] = pwl + 3 * 16384;  P.PW2l[1] = pwl + 1 * 16384;
        P.bias[0] = b1_iu;            P.bias[1] = b1_ui;
        P.deg[0] = deg_u;             P.deg[1] = deg_i;
        P.Cin[0] = nullptr;           P.Cin[1] = nullptr;
        P.Cf[0] = hu;                 P.Cf[1] = hi;
        gemm_pp<128, 256, true, true, false, true>
            <<<dim3(2, MT_U, 2), 256>>>(P);
    }

    // idx4: p = h @ Wl2 dual GEMM (fp32 out into reused agg buffers)
    {
        GP P;
        P.M[0] = N_USER;              P.M[1] = N_ITEM;
        P.A1[0] = hu;                 P.A1[1] = hi;
        P.A2[0] = nullptr;            P.A2[1] = nullptr;
        P.PW1h[0] = pwh + 4 * 16384;  P.PW1h[1] = pwh + 6 * 16384;
        P.PW1l[0] = pwl + 4 * 16384;  P.PW1l[1] = pwl + 6 * 16384;
        P.PW2h[0] = nullptr;          P.PW2h[1] = nullptr;
        P.PW2l[0] = nullptr;          P.PW2l[1] = nullptr;
        P.bias[0] = nullptr;          P.bias[1] = nullptr;
        P.deg[0] = nullptr;           P.deg[1] = nullptr;
        P.Cin[0] = nullptr;           P.Cin[1] = nullptr;
        P.Cf[0] = a1u;                P.Cf[1] = a1i;
        gemm_pp<256, 128, false, false, false, false>
            <<<dim3(1, MT_U, 2), 256>>>(P);
    }

    // idx5: layer-2 scatter of transformed features
    {
        long long threads = (long long)NE * 32;
        scatter_p<<<(int)((threads + 255) / 256), 256>>>(src_u, dst_i);
    }

    // idx6: z = acc2/deg + h @ Wr2 + b2 dual GEMM
    {
        GP P;
        P.M[0] = N_USER;              P.M[1] = N_ITEM;
        P.A1[0] = hu;                 P.A1[1] = hi;
        P.A2[0] = nullptr;            P.A2[1] = nullptr;
        P.PW1h[0] = pwh + 7 * 16384;  P.PW1h[1] = pwh + 5 * 16384;
        P.PW1l[0] = pwl + 7 * 16384;  P.PW1l[1] = pwl + 5 * 16384;
        P.PW2h[0] = nullptr;          P.PW2h[1] = nullptr;
        P.PW2l[0] = nullptr;          P.PW2l[1] = nullptr;
        P.bias[0] = b2_iu;            P.bias[1] = b2_ui;
        P.deg[0] = deg_u;             P.deg[1] = deg_i;
        P.Cin[0] = c2u;               P.Cin[1] = c2i;
        P.Cf[0] = zu;                 P.Cf[1] = zi;
        gemm_pp<256, 128, false, true, true, false>
            <<<dim3(1, MT_U, 2), 256>>>(P);
    }

    // idx7: decode
    {
        long long threads = (long long)NL * 32;
        decode_kernel<<<(int)((threads + 255) / 256), 256>>>(label_src, label_dst, (float*)d_out);
    }
}

// round 12
// speedup vs baseline: 1.1238x; 1.0398x over previous
#include <cuda_runtime.h>
#include <cuda_bf16.h>
#include <cstdint>
#include <cstddef>

#define N_USER 50000
#define N_ITEM 20000
#define D_IN   128
#define D_HID  256
#define D_OUT  128
#define NE     300000
#define NL     200000

// ---------------- device scratch (static, allocation-free) ----------------
__device__ float g_deg_user[N_USER];
__device__ float g_deg_item[N_ITEM];
__device__ float g_agg1_item[N_ITEM * D_IN];   // later reused as p_item
__device__ float g_agg1_user[N_USER * D_IN];   // later reused as p_user
__device__ float g_h_item[N_ITEM * D_HID];
__device__ float g_h_user[N_USER * D_HID];
__device__ float g_acc2_item[N_ITEM * D_OUT];
__device__ float g_acc2_user[N_USER * D_OUT];
__device__ float g_z_item[N_ITEM * D_OUT];
__device__ float g_z_user[N_USER * D_OUT];
// W pre-packed into smem fragment-tuple layout (bf16x2 words, hi/lo)
__device__ uint32_t g_pwh[8 * 16384];
__device__ uint32_t g_pwl[8 * 16384];

// ---------------- helpers ----------------
__device__ __forceinline__ void split2(float x0, float x1, uint32_t& hi, uint32_t& lo) {
    __nv_bfloat162 h = __floats2bfloat162_rn(x0, x1);
    float r0 = x0 - __bfloat162float(__low2bfloat16(h));
    float r1 = x1 - __bfloat162float(__high2bfloat16(h));
    __nv_bfloat162 l = __floats2bfloat162_rn(r0, r1);
    hi = *reinterpret_cast<uint32_t*>(&h);
    lo = *reinterpret_cast<uint32_t*>(&l);
}

__device__ __forceinline__ void cp_async16(uint32_t dst, const void* src) {
    asm volatile("cp.async.cg.shared.global [%0], [%1], 16;"
                 :: "r"(dst), "l"(src) : "memory");
}
__device__ __forceinline__ void cp_async_commit() {
    asm volatile("cp.async.commit_group;" ::: "memory");
}
__device__ __forceinline__ void cp_async_wait0() {
    asm volatile("cp.async.wait_group 0;" ::: "memory");
}

// ---------------- fused zero fill ----------------
__global__ void zero_multi6(float4* p0, int n0, float4* p1, int n1,
                            float4* p2, int n2, float4* p3, int n3,
                            float4* p4, int n4, float4* p5, int n5) {
    int i = blockIdx.x * blockDim.x + threadIdx.x;
    float4 z = make_float4(0.f, 0.f, 0.f, 0.f);
    if (i < n0) p0[i] = z;
    if (i < n1) p1[i] = z;
    if (i < n2) p2[i] = z;
    if (i < n3) p3[i] = z;
    if (i < n4) p4[i] = z;
    if (i < n5) p5[i] = z;
}

// ---------------- pack W into frag-tuple layout (one launch) ------
// Packed layout per matrix (16384 words): widx = ((nblk*TPS + chunk) << 10) + t
//   t = pair*512 + wnb*128 + fg*16 + ft*4 + j
//   nt = 2*pair + (j>>1), b = j&1
//   n  = nblk*128 + wnb*32 + 8*nt + fg
//   k  = chunk*16 + 2*ft + 8*b       -> word packs (W[k][n], W[k+1][n])
#define PACK_WORK (8 * 16384)
__global__ void pack_w(const float* w0, const float* w1, const float* w2,
                       const float* w3, const float* w4, const float* w5,
                       const float* w6, const float* w7) {
    int i = blockIdx.x * blockDim.x + threadIdx.x;
    if (i >= PACK_WORK) return;
    int w = i >> 14;
    int widx = i & 16383;
    const float* src;
    int Ndim, TPS;
    switch (w) {
        case 0: src = w0; break;
        case 1: src = w1; break;
        case 2: src = w2; break;
        case 3: src = w3; break;
        case 4: src = w4; break;
        case 5: src = w5; break;
        case 6: src = w6; break;
        default: src = w7; break;
    }
    if (w < 4) { Ndim = 256; TPS = 8; }
    else       { Ndim = 128; TPS = 16; }
    int cb = widx >> 10;              // nblk*TPS + chunk
    int nblk = cb / TPS;
    int chunk = cb % TPS;
    int t = widx & 1023;
    int pair = t >> 9;
    int wnb = (t >> 7) & 3;
    int fg = (t >> 4) & 7;
    int ft = (t >> 2) & 3;
    int j = t & 3;
    int nt = 2 * pair + (j >> 1);
    int b = j & 1;
    int n = nblk * 128 + wnb * 32 + 8 * nt + fg;
    int k = chunk * 16 + 2 * ft + 8 * b;
    float v0 = __ldg(src + k * Ndim + n);
    float v1 = __ldg(src + (k + 1) * Ndim + n);
    uint32_t hw, lw;
    split2(v0, v1, hw, lw);
    g_pwh[i] = hw;
    g_pwl[i] = lw;
}

// ---------------- vectorized global reduction ----------------
__device__ __forceinline__ void red_add_v4(float* p, float4 v) {
    asm volatile("red.global.add.v4.f32 [%0], {%1, %2, %3, %4};"
                 :: "l"(p), "f"(v.x), "f"(v.y), "f"(v.z), "f"(v.w)
                 : "memory");
}

// ---------------- layer-1 edge scatter (128-dim) + degree count ----------------
__global__ void scatter_l1(const float* __restrict__ x_user,
                           const float* __restrict__ x_item,
                           const int* __restrict__ src,
                           const int* __restrict__ dst) {
    int gt = blockIdx.x * blockDim.x + threadIdx.x;
    int e = gt >> 5;
    int lane = gt & 31;
    if (e >= NE) return;
    int s = __ldg(src + e);
    int d = __ldg(dst + e);

    float4 vu = __ldg(&((const float4*)x_user)[s * 32 + lane]);
    red_add_v4(g_agg1_item + d * 128 + lane * 4, vu);

    float4 vi = __ldg(&((const float4*)x_item)[d * 32 + lane]);
    red_add_v4(g_agg1_user + s * 128 + lane * 4, vi);

    if (lane == 0) {
        atomicAdd(&g_deg_item[d], 1.f);
        atomicAdd(&g_deg_user[s], 1.f);
    }
}

// ---------------- layer-2 scatter of transformed features (128-dim) ----------------
__global__ void scatter_p(const int* __restrict__ src,
                          const int* __restrict__ dst) {
    int gt = blockIdx.x * blockDim.x + threadIdx.x;
    int e = gt >> 5;
    int lane = gt & 31;
    if (e >= NE) return;
    int s = __ldg(src + e);
    int d = __ldg(dst + e);

    float4 pu = __ldg(&((const float4*)g_agg1_user)[s * 32 + lane]);
    red_add_v4(g_acc2_item + d * 128 + lane * 4, pu);

    float4 pi = __ldg(&((const float4*)g_agg1_item)[d * 32 + lane]);
    red_add_v4(g_acc2_user + s * 128 + lane * 4, pi);
}

// ================= 3xBF16 mma.sync GEMM: BK=32, cp.async B, frag-major A ====
__device__ __forceinline__ void mma_bf16(float c[4],
                                         const uint32_t a[4],
                                         const uint32_t b[2]) {
    asm volatile(
        "mma.sync.aligned.m16n8k16.row.col.f32.bf16.bf16.f32 "
        "{%0,%1,%2,%3}, {%4,%5,%6,%7}, {%8,%9}, {%0,%1,%2,%3};"
        : "+f"(c[0]), "+f"(c[1]), "+f"(c[2]), "+f"(c[3])
        : "r"(a[0]), "r"(a[1]), "r"(a[2]), "r"(a[3]), "r"(b[0]), "r"(b[1]));
}

struct GP {
    int M[2];
    const float* A1[2];                 // fp32 A seg0 (scaled by 1/deg if SEG2)
    const float* A2[2];                 // fp32 A seg1 (SEG2 only)
    const uint32_t* PW1h[2];            // pre-packed W, frag-tuple layout
    const uint32_t* PW1l[2];
    const uint32_t* PW2h[2];
    const uint32_t* PW2l[2];
    const float* bias[2];
    const float* deg[2];
    const float* Cin[2];
    float* Cf[2];
};

// dynamic smem: AsH[2][2048] | AsL[2][2048] | BsH[2][2048] | BsL[2][2048]
#define GEMM_SMEM_BYTES (4 * 4096 * 4)

template <int K, int N, bool SEG2, bool HASBIAS, bool CACC, bool RELU>
__global__ __launch_bounds__(256, 2)
void gemm_pp32(GP P) {
    const int side = blockIdx.z;
    const int M = P.M[side];
    const int bm = blockIdx.y * 128;
    if (bm >= M) return;
    const int bn = blockIdx.x * 128;

    const float* __restrict__ A1 = P.A1[side];
    const float* __restrict__ A2 = P.A2[side];
    const uint32_t* __restrict__ PW1h = P.PW1h[side];
    const uint32_t* __restrict__ PW1l = P.PW1l[side];
    const uint32_t* __restrict__ PW2h = P.PW2h[side];
    const uint32_t* __restrict__ PW2l = P.PW2l[side];
    const float* __restrict__ bias = P.bias[side];
    const float* __restrict__ deg = P.deg[side];
    const float* __restrict__ Cin = P.Cin[side];
    float* __restrict__ Cout = P.Cf[side];

    extern __shared__ uint32_t smem[];
    uint32_t* AsH = smem;              // [2][2048]
    uint32_t* AsL = smem + 4096;
    uint32_t* BsH = smem + 8192;
    uint32_t* BsL = smem + 12288;

    const int tid = threadIdx.x;
    const int lane = tid & 31;
    const int w = tid >> 5;
    const int wmblk = w & 1;
    const int wm = wmblk * 64;
    const int wnb = w >> 1;
    const int wn = wnb * 32;
    const int fg = lane >> 2;
    const int ft = lane & 3;
    const int ftp = ft ^ ((fg >> 1) & 3);

    // ---- producer mappings (A: frag-tuple, per BK16 sub-block) ----
    const int arow = tid >> 1;
    const int khalf = tid & 1;
    const int am = bm + arow;
    const bool avalid = am < M;
    const int pwm = arow >> 6;
    const int pmt = (arow >> 4) & 3;
    const int pfg = arow & 7;
    const int prh = (arow >> 3) & 1;
    const int psw = (pfg >> 1) & 3;
    const int atbase = ((pwm * 4 + pmt) * 8 + pfg) * 16 + prh * 2 + khalf;
    // consumer bases (within a BK16 sub-block of 1024 words)
    const int aidx = ((wmblk * 4) * 8 + fg) * 16;
    const int bidx0 = wnb * 128 + fg * 16 + ft * 4;

    float ascale = 1.f;
    if (SEG2) ascale = avalid ? (1.f / fmaxf(__ldg(deg + am), 1.f)) : 0.f;

    float acc[4][4][4];
#pragma unroll
    for (int i = 0; i < 4; i++)
#pragma unroll
        for (int j = 0; j < 4; j++)
#pragma unroll
            for (int r = 0; r < 4; r++) acc[i][j][r] = 0.f;

    const int TPS32 = K / 32;            // chunk32s per segment
    const int TPS16 = K / 16;
    const int NT = (SEG2 ? 2 : 1) * TPS32;
    const int nblk = blockIdx.x;

    // B copy: thread copies words [tid*4] and [1024 + tid*4] of the 2048-word stage
    auto cp_b = [&](int buf, int t) {
        const bool seg1 = SEG2 && (t >= TPS32);
        const int cl = seg1 ? (t - TPS32) : t;
        const uint32_t* Ph = seg1 ? PW2h : PW1h;
        const uint32_t* Pl = seg1 ? PW2l : PW1l;
        const int off = ((nblk * TPS16 + cl * 2) << 10) + (tid << 2);
        uint32_t dh = (uint32_t)__cvta_generic_to_shared(&BsH[buf * 2048 + (tid << 2)]);
        uint32_t dl = (uint32_t)__cvta_generic_to_shared(&BsL[buf * 2048 + (tid << 2)]);
        cp_async16(dh, Ph + off);
        cp_async16(dh + 4096, Ph + off + 1024);
        cp_async16(dl, Pl + off);
        cp_async16(dl + 4096, Pl + off + 1024);
        cp_async_commit();
    };

    // A load: 16 floats (k = cl*32 + khalf*8 + {0..7} and +16)
    auto ldg_a = [&](int t, float4 pa[4]) {
        const bool seg1 = SEG2 && (t >= TPS32);
        const int cl = seg1 ? (t - TPS32) : t;
        const float* A = seg1 ? A2 : A1;
        pa[0] = make_float4(0.f, 0.f, 0.f, 0.f);
        pa[1] = pa[0]; pa[2] = pa[0]; pa[3] = pa[0];
        if (avalid) {
            const float* ap = A + (size_t)am * K + cl * 32 + khalf * 8;
            pa[0] = *(const float4*)ap;
            pa[1] = *(const float4*)(ap + 4);
            pa[2] = *(const float4*)(ap + 16);
            pa[3] = *(const float4*)(ap + 20);
            if (SEG2 && !seg1) {
#pragma unroll
                for (int q = 0; q < 4; q++) {
                    pa[q].x *= ascale; pa[q].y *= ascale;
                    pa[q].z *= ascale; pa[q].w *= ascale;
                }
            }
        }
    };

    auto sts_a = [&](int buf, const float4 pa[4]) {
#pragma unroll
        for (int s = 0; s < 2; s++) {
            float f[8] = {pa[2 * s].x, pa[2 * s].y, pa[2 * s].z, pa[2 * s].w,
                          pa[2 * s + 1].x, pa[2 * s + 1].y, pa[2 * s + 1].z, pa[2 * s + 1].w};
#pragma unroll
            for (int j = 0; j < 4; j++) {
                uint32_t hw, lw;
                split2(f[2 * j], f[2 * j + 1], hw, lw);
                int widx = buf * 2048 + s * 1024 + atbase + (j ^ psw) * 4;
                AsH[widx] = hw;
                AsL[widx] = lw;
            }
        }
    };

    // ---- prologue ----
    {
        cp_b(0, 0);
        float4 pa[4];
        ldg_a(0, pa);
        sts_a(0, pa);
        cp_async_wait0();
    }
    __syncthreads();

    int buf = 0;
    for (int t = 0; t < NT; t++) {
        const bool more = (t + 1) < NT;
        float4 pa[4];
        if (more) {
            cp_b(buf ^ 1, t + 1);      // async into free buffer
            ldg_a(t + 1, pa);
        }

#pragma unroll
        for (int s = 0; s < 2; s++) {
            const int ab = buf * 2048 + s * 1024;
            // A-hi frags: 4 x LDS.128
            uint32_t ah[4][4];
#pragma unroll
            for (int mt = 0; mt < 4; mt++) {
                uint4 v = *(const uint4*)&AsH[ab + aidx + mt * 128 + ftp * 4];
                ah[mt][0] = v.x; ah[mt][1] = v.z; ah[mt][2] = v.y; ah[mt][3] = v.w;
            }
            // B-hi frags: 2 x LDS.128
            uint32_t bh[4][2];
            {
                uint4 t0 = *(const uint4*)&BsH[ab + bidx0];
                uint4 t1 = *(const uint4*)&BsH[ab + bidx0 + 512];
                bh[0][0] = t0.x; bh[0][1] = t0.y; bh[1][0] = t0.z; bh[1][1] = t0.w;
                bh[2][0] = t1.x; bh[2][1] = t1.y; bh[3][0] = t1.z; bh[3][1] = t1.w;
            }
            // pass 1: Ah * Bh
#pragma unroll
            for (int mt = 0; mt < 4; mt++)
#pragma unroll
                for (int nt = 0; nt < 4; nt++) mma_bf16(acc[mt][nt], ah[mt], bh[nt]);

            // pass 2: Ah * Bl
            {
                uint32_t bl[4][2];
                uint4 t0 = *(const uint4*)&BsL[ab + bidx0];
                uint4 t1 = *(const uint4*)&BsL[ab + bidx0 + 512];
                bl[0][0] = t0.x; bl[0][1] = t0.y; bl[1][0] = t0.z; bl[1][1] = t0.w;
                bl[2][0] = t1.x; bl[2][1] = t1.y; bl[3][0] = t1.z; bl[3][1] = t1.w;
#pragma unroll
                for (int mt = 0; mt < 4; mt++)
#pragma unroll
                    for (int nt = 0; nt < 4; nt++) mma_bf16(acc[mt][nt], ah[mt], bl[nt]);
            }

            // pass 3: Al * Bh
            {
                uint32_t al[4][4];
#pragma unroll
                for (int mt = 0; mt < 4; mt++) {
                    uint4 v = *(const uint4*)&AsL[ab + aidx + mt * 128 + ftp * 4];
                    al[mt][0] = v.x; al[mt][1] = v.z; al[mt][2] = v.y; al[mt][3] = v.w;
                }
#pragma unroll
                for (int mt = 0; mt < 4; mt++)
#pragma unroll
                    for (int nt = 0; nt < 4; nt++) mma_bf16(acc[mt][nt], al[mt], bh[nt]);
            }
        }

        if (more) {
            sts_a(buf ^ 1, pa);
            cp_async_wait0();
            __syncthreads();
            buf ^= 1;
        }
    }

    // ---------------- epilogue (fp32 float2 stores) ----------------
#pragma unroll
    for (int nt = 0; nt < 4; nt++) {
        const int c0 = bn + wn + 8 * nt + 2 * ft;
        float b0 = 0.f, b1 = 0.f;
        if (HASBIAS) {
            b0 = __ldg(bias + c0);
            b1 = __ldg(bias + c0 + 1);
        }
#pragma unroll
        for (int mt = 0; mt < 4; mt++) {
            const int r0 = bm + wm + 16 * mt + fg;
            const int r1 = r0 + 8;
            float o00 = acc[mt][nt][0] + b0;
            float o01 = acc[mt][nt][1] + b1;
            float o10 = acc[mt][nt][2] + b0;
            float o11 = acc[mt][nt][3] + b1;
            if (CACC) {
                if (r0 < M) {
                    float id0 = 1.f / fmaxf(__ldg(deg + r0), 1.f);
                    float2 ci = *(const float2*)(Cin + (size_t)r0 * N + c0);
                    o00 += ci.x * id0;
                    o01 += ci.y * id0;
                }
                if (r1 < M) {
                    float id1 = 1.f / fmaxf(__ldg(deg + r1), 1.f);
                    float2 ci = *(const float2*)(Cin + (size_t)r1 * N + c0);
                    o10 += ci.x * id1;
                    o11 += ci.y * id1;
                }
            }
            if (RELU) {
                o00 = fmaxf(o00, 0.f); o01 = fmaxf(o01, 0.f);
                o10 = fmaxf(o10, 0.f); o11 = fmaxf(o11, 0.f);
            }
            if (r0 < M) *(float2*)(Cout + (size_t)r0 * N + c0) = make_float2(o00, o01);
            if (r1 < M) *(float2*)(Cout + (size_t)r1 * N + c0) = make_float2(o10, o11);
        }
    }
}

// ---------------- decode ----------------
__global__ void decode_kernel(const int* __restrict__ ls,
                              const int* __restrict__ ld,
                              float* __restrict__ out) {
    int gt = blockIdx.x * blockDim.x + threadIdx.x;
    int i = gt >> 5;
    int lane = gt & 31;
    if (i >= NL) return;
    int a = __ldg(ls + i);
    int b = __ldg(ld + i);
    float4 u = ((const float4*)g_z_user)[a * 32 + lane];
    float4 v = ((const float4*)g_z_item)[b * 32 + lane];
    float s = u.x * v.x + u.y * v.y + u.z * v.z + u.w * v.w;
#pragma unroll
    for (int o = 16; o > 0; o >>= 1) s += __shfl_down_sync(0xffffffffu, s, o);
    if (lane == 0) {
        out[i] = -s;
        out[NL + i] = s;
    }
}

// ---------------- host launch ----------------
extern "C" void kernel_launch(void* const* d_in, const int* in_sizes, int n_in,
                              void* d_out, int out_size) {
    const float* x_user = (const float*)d_in[0];
    const float* x_item = (const float*)d_in[1];
    const float* Wl1_ui = (const float*)d_in[2];
    const float* Wr1_ui = (const float*)d_in[3];
    const float* b1_ui  = (const float*)d_in[4];
    const float* Wl1_iu = (const float*)d_in[5];
    const float* Wr1_iu = (const float*)d_in[6];
    const float* b1_iu  = (const float*)d_in[7];
    const float* Wl2_ui = (const float*)d_in[8];
    const float* Wr2_ui = (const float*)d_in[9];
    const float* b2_ui  = (const float*)d_in[10];
    const float* Wl2_iu = (const float*)d_in[11];
    const float* Wr2_iu = (const float*)d_in[12];
    const float* b2_iu  = (const float*)d_in[13];
    const int* src_u     = (const int*)d_in[14];
    const int* dst_i     = (const int*)d_in[15];
    const int* label_src = (const int*)d_in[16];
    const int* label_dst = (const int*)d_in[17];

    float *deg_u, *deg_i, *a1i, *a1u, *hi, *hu, *c2i, *c2u, *zi, *zu;
    uint32_t *pwh, *pwl;
    cudaGetSymbolAddress((void**)&deg_u, g_deg_user);
    cudaGetSymbolAddress((void**)&deg_i, g_deg_item);
    cudaGetSymbolAddress((void**)&a1i, g_agg1_item);
    cudaGetSymbolAddress((void**)&a1u, g_agg1_user);
    cudaGetSymbolAddress((void**)&hi, g_h_item);
    cudaGetSymbolAddress((void**)&hu, g_h_user);
    cudaGetSymbolAddress((void**)&c2i, g_acc2_item);
    cudaGetSymbolAddress((void**)&c2u, g_acc2_user);
    cudaGetSymbolAddress((void**)&zi, g_z_item);
    cudaGetSymbolAddress((void**)&zu, g_z_user);
    cudaGetSymbolAddress((void**)&pwh, g_pwh);
    cudaGetSymbolAddress((void**)&pwl, g_pwl);

    // enable 64KB dynamic smem (host-side attribute set; idempotent)
    cudaFuncSetAttribute(gemm_pp32<128, 256, true, true, false, true>,
                         cudaFuncAttributeMaxDynamicSharedMemorySize, GEMM_SMEM_BYTES);
    cudaFuncSetAttribute(gemm_pp32<256, 128, false, false, false, false>,
                         cudaFuncAttributeMaxDynamicSharedMemorySize, GEMM_SMEM_BYTES);
    cudaFuncSetAttribute(gemm_pp32<256, 128, false, true, true, false>,
                         cudaFuncAttributeMaxDynamicSharedMemorySize, GEMM_SMEM_BYTES);

    const int MT_U = (N_USER + 127) / 128;   // 391

    // idx0: zero accumulators + degree counters
    {
        int n0 = N_ITEM * D_IN / 4, n1 = N_USER * D_IN / 4;
        int n2 = N_USER / 4, n3 = N_ITEM / 4;
        int n4 = N_ITEM * D_OUT / 4, n5 = N_USER * D_OUT / 4;
        zero_multi6<<<(n1 + 255) / 256, 256>>>((float4*)a1i, n0, (float4*)a1u, n1,
                                               (float4*)deg_u, n2, (float4*)deg_i, n3,
                                               (float4*)c2i, n4, (float4*)c2u, n5);
    }

    // idx1: pack weights (frag-tuple layout)
    pack_w<<<(PACK_WORK + 255) / 256, 256>>>(Wl1_ui, Wr1_ui, Wl1_iu, Wr1_iu,
                                             Wl2_ui, Wr2_ui, Wl2_iu, Wr2_iu);

    // idx2: layer-1 scatter + degrees
    {
        long long threads = (long long)NE * 32;
        scatter_l1<<<(int)((threads + 255) / 256), 256>>>(x_user, x_item, src_u, dst_i);
    }

    // idx3 (profiler capture slot): layer-1 dual GEMM -> h (fp32)
    {
        GP P;
        P.M[0] = N_USER;              P.M[1] = N_ITEM;
        P.A1[0] = a1u;                P.A1[1] = a1i;
        P.A2[0] = x_user;             P.A2[1] = x_item;
        P.PW1h[0] = pwh + 2 * 16384;  P.PW1h[1] = pwh + 0 * 16384;
        P.PW1l[0] = pwl + 2 * 16384;  P.PW1l[1] = pwl + 0 * 16384;
        P.PW2h[0] = pwh + 3 * 16384;  P.PW2h[1] = pwh + 1 * 16384;
        P.PW2l[0] = pwl + 3 * 16384;  P.PW2l[1] = pwl + 1 * 16384;
        P.bias[0] = b1_iu;            P.bias[1] = b1_ui;
        P.deg[0] = deg_u;             P.deg[1] = deg_i;
        P.Cin[0] = nullptr;           P.Cin[1] = nullptr;
        P.Cf[0] = hu;                 P.Cf[1] = hi;
        gemm_pp32<128, 256, true, true, false, true>
            <<<dim3(2, MT_U, 2), 256, GEMM_SMEM_BYTES>>>(P);
    }

    // idx4: p = h @ Wl2 dual GEMM (fp32 out into reused agg buffers)
    {
        GP P;
        P.M[0] = N_USER;              P.M[1] = N_ITEM;
        P.A1[0] = hu;                 P.A1[1] = hi;
        P.A2[0] = nullptr;            P.A2[1] = nullptr;
        P.PW1h[0] = pwh + 4 * 16384;  P.PW1h[1] = pwh + 6 * 16384;
        P.PW1l[0] = pwl + 4 * 16384;  P.PW1l[1] = pwl + 6 * 16384;
        P.PW2h[0] = nullptr;          P.PW2h[1] = nullptr;
        P.PW2l[0] = nullptr;          P.PW2l[1] = nullptr;
        P.bias[0] = nullptr;          P.bias[1] = nullptr;
        P.deg[0] = nullptr;           P.deg[1] = nullptr;
        P.Cin[0] = nullptr;           P.Cin[1] = nullptr;
        P.Cf[0] = a1u;                P.Cf[1] = a1i;
        gemm_pp32<256, 128, false, false, false, false>
            <<<dim3(1, MT_U, 2), 256, GEMM_SMEM_BYTES>>>(P);
    }

    // idx5: layer-2 scatter of transformed features
    {
        long long threads = (long long)NE * 32;
        scatter_p<<<(int)((threads + 255) / 256), 256>>>(src_u, dst_i);
    }

    // idx6: z = acc2/deg + h @ Wr2 + b2 dual GEMM
    {
        GP P;
        P.M[0] = N_USER;              P.M[1] = N_ITEM;
        P.A1[0] = hu;                 P.A1[1] = hi;
        P.A2[0] = nullptr;            P.A2[1] = nullptr;
        P.PW1h[0] = pwh + 7 * 16384;  P.PW1h[1] = pwh + 5 * 16384;
        P.PW1l[0] = pwl + 7 * 16384;  P.PW1l[1] = pwl + 5 * 16384;
        P.PW2h[0] = nullptr;          P.PW2h[1] = nullptr;
        P.PW2l[0] = nullptr;          P.PW2l[1] = nullptr;
        P.bias[0] = b2_iu;            P.bias[1] = b2_ui;
        P.deg[0] = deg_u;             P.deg[1] = deg_i;
        P.Cin[0] = c2u;               P.Cin[1] = c2i;
        P.Cf[0] = zu;                 P.Cf[1] = zi;
        gemm_pp32<256, 128, false, true, true, false>
            <<<dim3(1, MT_U, 2), 256, GEMM_SMEM_BYTES>>>(P);
    }

    // idx7: decode
    {
        long long threads = (long long)NL * 32;
        decode_kernel<<<(int)((threads + 255) / 256), 256>>>(label_src, label_dst, (float*)d_out);
    }
}

// round 13
// speedup vs baseline: 1.2571x; 1.1186x over previous
#include <cuda_runtime.h>
#include <cuda_bf16.h>
#include <cstdint>
#include <cstddef>

#define N_USER 50000
#define N_ITEM 20000
#define D_IN   128
#define D_HID  256
#define D_OUT  128
#define NE     300000
#define NL     200000

// ---------------- device scratch (static, allocation-free) ----------------
__device__ float g_agg1_item[N_ITEM * D_IN];   // later reused as p_item
__device__ float g_agg1_user[N_USER * D_IN];   // later reused as p_user
__device__ float g_h_item[N_ITEM * D_HID];
__device__ float g_h_user[N_USER * D_HID];
__device__ float g_acc2_item[N_ITEM * D_OUT];
__device__ float g_acc2_user[N_USER * D_OUT];
__device__ float g_z_item[N_ITEM * D_OUT];
__device__ float g_z_user[N_USER * D_OUT];
// W pre-packed into smem fragment-tuple layout (bf16x2 words, hi/lo)
__device__ uint32_t g_pwh[8 * 16384];
__device__ uint32_t g_pwl[8 * 16384];
// CSR structures
__device__ int g_cnt_i[N_ITEM];
__device__ int g_cnt_u[N_USER];
__device__ int g_off_i[N_ITEM + 1];
__device__ int g_off_u[N_USER + 1];
__device__ int g_cur_i[N_ITEM];
__device__ int g_cur_u[N_USER];
__device__ int g_eidx_i[NE];    // per item: user indices
__device__ int g_eidx_u[NE];    // per user: item indices

// ---------------- helpers ----------------
__device__ __forceinline__ void split2(float x0, float x1, uint32_t& hi, uint32_t& lo) {
    __nv_bfloat162 h = __floats2bfloat162_rn(x0, x1);
    float r0 = x0 - __bfloat162float(__low2bfloat16(h));
    float r1 = x1 - __bfloat162float(__high2bfloat16(h));
    __nv_bfloat162 l = __floats2bfloat162_rn(r0, r1);
    hi = *reinterpret_cast<uint32_t*>(&h);
    lo = *reinterpret_cast<uint32_t*>(&l);
}

__device__ __forceinline__ void cp_async16(uint32_t dst, const void* src) {
    asm volatile("cp.async.cg.shared.global [%0], [%1], 16;"
                 :: "r"(dst), "l"(src) : "memory");
}
__device__ __forceinline__ void cp_async_commit() {
    asm volatile("cp.async.commit_group;" ::: "memory");
}
__device__ __forceinline__ void cp_async_wait0() {
    asm volatile("cp.async.wait_group 0;" ::: "memory");
}

// ---------------- CSR build ----------------
__global__ void zero_cnt() {
    int i = blockIdx.x * blockDim.x + threadIdx.x;
    if (i < N_USER) g_cnt_u[i] = 0;
    if (i < N_ITEM) g_cnt_i[i] = 0;
}

__global__ void hist_k(const int* __restrict__ src, const int* __restrict__ dst) {
    int e = blockIdx.x * blockDim.x + threadIdx.x;
    if (e >= NE) return;
    atomicAdd(&g_cnt_i[__ldg(dst + e)], 1);
    atomicAdd(&g_cnt_u[__ldg(src + e)], 1);
}

// one block per array: exclusive scan of counts -> off, cur
__global__ __launch_bounds__(1024) void scan_k() {
    const int which = blockIdx.x;
    const int n = which ? N_USER : N_ITEM;
    const int* cnt = which ? g_cnt_u : g_cnt_i;
    int* off = which ? g_off_u : g_off_i;
    int* cur = which ? g_cur_u : g_cur_i;
    const int t = threadIdx.x;
    const int lane = t & 31;
    const int wid = t >> 5;
    __shared__ int wsum[32];
    __shared__ int sCarry;
    if (t == 0) sCarry = 0;
    __syncthreads();
    for (int base = 0; base < n; base += 1024) {
        int idx = base + t;
        int v = (idx < n) ? cnt[idx] : 0;
        int x = v;
#pragma unroll
        for (int o = 1; o < 32; o <<= 1) {
            int y = __shfl_up_sync(0xffffffffu, x, o);
            if (lane >= o) x += y;
        }
        if (lane == 31) wsum[wid] = x;
        __syncthreads();
        if (wid == 0) {
            int s = wsum[lane];
#pragma unroll
            for (int o = 1; o < 32; o <<= 1) {
                int y = __shfl_up_sync(0xffffffffu, s, o);
                if (lane >= o) s += y;
            }
            wsum[lane] = s;
        }
        __syncthreads();
        int warppre = (wid > 0) ? wsum[wid - 1] : 0;
        int incl = x + warppre + sCarry;
        int excl = incl - v;
        if (idx < n) { off[idx] = excl; cur[idx] = excl; }
        __syncthreads();
        if (t == 1023) sCarry = incl;
        __syncthreads();
    }
    if (t == 0) off[n] = sCarry;
}

__global__ void fill_k(const int* __restrict__ src, const int* __restrict__ dst) {
    int e = blockIdx.x * blockDim.x + threadIdx.x;
    if (e >= NE) return;
    int s = __ldg(src + e);
    int d = __ldg(dst + e);
    int p = atomicAdd(&g_cur_i[d], 1);
    g_eidx_i[p] = s;
    int q = atomicAdd(&g_cur_u[s], 1);
    g_eidx_u[q] = d;
}

// ---------------- mean aggregation: warp per destination node ----------------
// first N_ITEM warps: out = mean over eidx_i bucket of fA rows
// next N_USER warps: out = mean over eidx_u bucket of fB rows
__global__ void agg_dual(const float* __restrict__ fA, const float* __restrict__ fB,
                         float* __restrict__ outA, float* __restrict__ outB) {
    int gw = (blockIdx.x * blockDim.x + threadIdx.x) >> 5;
    int lane = threadIdx.x & 31;
    const float* feat;
    const int* eidx;
    const int* off;
    float* out;
    int node;
    if (gw < N_ITEM) {
        node = gw; feat = fA; eidx = g_eidx_i; off = g_off_i; out = outA;
    } else if (gw < N_ITEM + N_USER) {
        node = gw - N_ITEM; feat = fB; eidx = g_eidx_u; off = g_off_u; out = outB;
    } else {
        return;
    }
    int b0 = __ldg(off + node);
    int b1 = __ldg(off + node + 1);
    float4 a0 = make_float4(0.f, 0.f, 0.f, 0.f);
    float4 a1 = a0;
    int j = b0;
    for (; j + 2 <= b1; j += 2) {
        int i0 = __ldg(eidx + j);
        int i1 = __ldg(eidx + j + 1);
        float4 v0 = __ldg(&((const float4*)feat)[i0 * 32 + lane]);
        float4 v1 = __ldg(&((const float4*)feat)[i1 * 32 + lane]);
        a0.x += v0.x; a0.y += v0.y; a0.z += v0.z; a0.w += v0.w;
        a1.x += v1.x; a1.y += v1.y; a1.z += v1.z; a1.w += v1.w;
    }
    if (j < b1) {
        int i0 = __ldg(eidx + j);
        float4 v0 = __ldg(&((const float4*)feat)[i0 * 32 + lane]);
        a0.x += v0.x; a0.y += v0.y; a0.z += v0.z; a0.w += v0.w;
    }
    float inv = 1.f / fmaxf((float)(b1 - b0), 1.f);
    float4 acc;
    acc.x = (a0.x + a1.x) * inv;
    acc.y = (a0.y + a1.y) * inv;
    acc.z = (a0.z + a1.z) * inv;
    acc.w = (a0.w + a1.w) * inv;
    ((float4*)out)[node * 32 + lane] = acc;
}

// ---------------- pack W into frag-tuple layout ----------------
#define PACK_WORK (8 * 16384)
__global__ void pack_w(const float* w0, const float* w1, const float* w2,
                       const float* w3, const float* w4, const float* w5,
                       const float* w6, const float* w7) {
    int i = blockIdx.x * blockDim.x + threadIdx.x;
    if (i >= PACK_WORK) return;
    int w = i >> 14;
    int widx = i & 16383;
    const float* src;
    int Ndim, TPS;
    switch (w) {
        case 0: src = w0; break;
        case 1: src = w1; break;
        case 2: src = w2; break;
        case 3: src = w3; break;
        case 4: src = w4; break;
        case 5: src = w5; break;
        case 6: src = w6; break;
        default: src = w7; break;
    }
    if (w < 4) { Ndim = 256; TPS = 8; }
    else       { Ndim = 128; TPS = 16; }
    int cb = widx >> 10;
    int nblk = cb / TPS;
    int chunk = cb % TPS;
    int t = widx & 1023;
    int pair = t >> 9;
    int wnb = (t >> 7) & 3;
    int fg = (t >> 4) & 7;
    int ft = (t >> 2) & 3;
    int j = t & 3;
    int nt = 2 * pair + (j >> 1);
    int b = j & 1;
    int n = nblk * 128 + wnb * 32 + 8 * nt + fg;
    int k = chunk * 16 + 2 * ft + 8 * b;
    float v0 = __ldg(src + k * Ndim + n);
    float v1 = __ldg(src + (k + 1) * Ndim + n);
    uint32_t hw, lw;
    split2(v0, v1, hw, lw);
    g_pwh[i] = hw;
    g_pwl[i] = lw;
}

// ================= 3xBF16 mma.sync GEMM: BK=32, cp.async B, frag-major A ====
__device__ __forceinline__ void mma_bf16(float c[4],
                                         const uint32_t a[4],
                                         const uint32_t b[2]) {
    asm volatile(
        "mma.sync.aligned.m16n8k16.row.col.f32.bf16.bf16.f32 "
        "{%0,%1,%2,%3}, {%4,%5,%6,%7}, {%8,%9}, {%0,%1,%2,%3};"
        : "+f"(c[0]), "+f"(c[1]), "+f"(c[2]), "+f"(c[3])
        : "r"(a[0]), "r"(a[1]), "r"(a[2]), "r"(a[3]), "r"(b[0]), "r"(b[1]));
}

struct GP {
    int M[2];
    const float* A1[2];                 // fp32 A seg0 (already mean-scaled)
    const float* A2[2];                 // fp32 A seg1 (SEG2 only)
    const uint32_t* PW1h[2];
    const uint32_t* PW1l[2];
    const uint32_t* PW2h[2];
    const uint32_t* PW2l[2];
    const float* bias[2];
    const float* Cin[2];                // mean-agg to add (CACC)
    float* Cf[2];
};

#define GEMM_SMEM_BYTES (4 * 4096 * 4)

template <int K, int N, bool SEG2, bool HASBIAS, bool CACC, bool RELU>
__global__ __launch_bounds__(256, 2)
void gemm_pp32(GP P) {
    const int side = blockIdx.z;
    const int M = P.M[side];
    const int bm = blockIdx.y * 128;
    if (bm >= M) return;
    const int bn = blockIdx.x * 128;

    const float* __restrict__ A1 = P.A1[side];
    const float* __restrict__ A2 = P.A2[side];
    const uint32_t* __restrict__ PW1h = P.PW1h[side];
    const uint32_t* __restrict__ PW1l = P.PW1l[side];
    const uint32_t* __restrict__ PW2h = P.PW2h[side];
    const uint32_t* __restrict__ PW2l = P.PW2l[side];
    const float* __restrict__ bias = P.bias[side];
    const float* __restrict__ Cin = P.Cin[side];
    float* __restrict__ Cout = P.Cf[side];

    extern __shared__ uint32_t smem[];
    uint32_t* AsH = smem;              // [2][2048]
    uint32_t* AsL = smem + 4096;
    uint32_t* BsH = smem + 8192;
    uint32_t* BsL = smem + 12288;

    const int tid = threadIdx.x;
    const int lane = tid & 31;
    const int w = tid >> 5;
    const int wmblk = w & 1;
    const int wm = wmblk * 64;
    const int wnb = w >> 1;
    const int wn = wnb * 32;
    const int fg = lane >> 2;
    const int ft = lane & 3;
    const int ftp = ft ^ ((fg >> 1) & 3);

    const int arow = tid >> 1;
    const int khalf = tid & 1;
    const int am = bm + arow;
    const bool avalid = am < M;
    const int pwm = arow >> 6;
    const int pmt = (arow >> 4) & 3;
    const int pfg = arow & 7;
    const int prh = (arow >> 3) & 1;
    const int psw = (pfg >> 1) & 3;
    const int atbase = ((pwm * 4 + pmt) * 8 + pfg) * 16 + prh * 2 + khalf;
    const int aidx = ((wmblk * 4) * 8 + fg) * 16;
    const int bidx0 = wnb * 128 + fg * 16 + ft * 4;

    float acc[4][4][4];
#pragma unroll
    for (int i = 0; i < 4; i++)
#pragma unroll
        for (int j = 0; j < 4; j++)
#pragma unroll
            for (int r = 0; r < 4; r++) acc[i][j][r] = 0.f;

    const int TPS32 = K / 32;
    const int TPS16 = K / 16;
    const int NT = (SEG2 ? 2 : 1) * TPS32;
    const int nblk = blockIdx.x;

    auto cp_b = [&](int buf, int t) {
        const bool seg1 = SEG2 && (t >= TPS32);
        const int cl = seg1 ? (t - TPS32) : t;
        const uint32_t* Ph = seg1 ? PW2h : PW1h;
        const uint32_t* Pl = seg1 ? PW2l : PW1l;
        const int off = ((nblk * TPS16 + cl * 2) << 10) + (tid << 2);
        uint32_t dh = (uint32_t)__cvta_generic_to_shared(&BsH[buf * 2048 + (tid << 2)]);
        uint32_t dl = (uint32_t)__cvta_generic_to_shared(&BsL[buf * 2048 + (tid << 2)]);
        cp_async16(dh, Ph + off);
        cp_async16(dh + 4096, Ph + off + 1024);
        cp_async16(dl, Pl + off);
        cp_async16(dl + 4096, Pl + off + 1024);
        cp_async_commit();
    };

    auto ldg_a = [&](int t, float4 pa[4]) {
        const bool seg1 = SEG2 && (t >= TPS32);
        const int cl = seg1 ? (t - TPS32) : t;
        const float* A = seg1 ? A2 : A1;
        pa[0] = make_float4(0.f, 0.f, 0.f, 0.f);
        pa[1] = pa[0]; pa[2] = pa[0]; pa[3] = pa[0];
        if (avalid) {
            const float* ap = A + (size_t)am * K + cl * 32 + khalf * 8;
            pa[0] = *(const float4*)ap;
            pa[1] = *(const float4*)(ap + 4);
            pa[2] = *(const float4*)(ap + 16);
            pa[3] = *(const float4*)(ap + 20);
        }
    };

    auto sts_a = [&](int buf, const float4 pa[4]) {
#pragma unroll
        for (int s = 0; s < 2; s++) {
            float f[8] = {pa[2 * s].x, pa[2 * s].y, pa[2 * s].z, pa[2 * s].w,
                          pa[2 * s + 1].x, pa[2 * s + 1].y, pa[2 * s + 1].z, pa[2 * s + 1].w};
#pragma unroll
            for (int j = 0; j < 4; j++) {
                uint32_t hw, lw;
                split2(f[2 * j], f[2 * j + 1], hw, lw);
                int widx = buf * 2048 + s * 1024 + atbase + (j ^ psw) * 4;
                AsH[widx] = hw;
                AsL[widx] = lw;
            }
        }
    };

    {
        cp_b(0, 0);
        float4 pa[4];
        ldg_a(0, pa);
        sts_a(0, pa);
        cp_async_wait0();
    }
    __syncthreads();

    int buf = 0;
    for (int t = 0; t < NT; t++) {
        const bool more = (t + 1) < NT;
        float4 pa[4];
        if (more) {
            cp_b(buf ^ 1, t + 1);
            ldg_a(t + 1, pa);
        }

#pragma unroll
        for (int s = 0; s < 2; s++) {
            const int ab = buf * 2048 + s * 1024;
            uint32_t ah[4][4];
#pragma unroll
            for (int mt = 0; mt < 4; mt++) {
                uint4 v = *(const uint4*)&AsH[ab + aidx + mt * 128 + ftp * 4];
                ah[mt][0] = v.x; ah[mt][1] = v.z; ah[mt][2] = v.y; ah[mt][3] = v.w;
            }
            uint32_t bh[4][2];
            {
                uint4 t0 = *(const uint4*)&BsH[ab + bidx0];
                uint4 t1 = *(const uint4*)&BsH[ab + bidx0 + 512];
                bh[0][0] = t0.x; bh[0][1] = t0.y; bh[1][0] = t0.z; bh[1][1] = t0.w;
                bh[2][0] = t1.x; bh[2][1] = t1.y; bh[3][0] = t1.z; bh[3][1] = t1.w;
            }
#pragma unroll
            for (int mt = 0; mt < 4; mt++)
#pragma unroll
                for (int nt = 0; nt < 4; nt++) mma_bf16(acc[mt][nt], ah[mt], bh[nt]);

            {
                uint32_t bl[4][2];
                uint4 t0 = *(const uint4*)&BsL[ab + bidx0];
                uint4 t1 = *(const uint4*)&BsL[ab + bidx0 + 512];
                bl[0][0] = t0.x; bl[0][1] = t0.y; bl[1][0] = t0.z; bl[1][1] = t0.w;
                bl[2][0] = t1.x; bl[2][1] = t1.y; bl[3][0] = t1.z; bl[3][1] = t1.w;
#pragma unroll
                for (int mt = 0; mt < 4; mt++)
#pragma unroll
                    for (int nt = 0; nt < 4; nt++) mma_bf16(acc[mt][nt], ah[mt], bl[nt]);
            }

            {
                uint32_t al[4][4];
#pragma unroll
                for (int mt = 0; mt < 4; mt++) {
                    uint4 v = *(const uint4*)&AsL[ab + aidx + mt * 128 + ftp * 4];
                    al[mt][0] = v.x; al[mt][1] = v.z; al[mt][2] = v.y; al[mt][3] = v.w;
                }
#pragma unroll
                for (int mt = 0; mt < 4; mt++)
#pragma unroll
                    for (int nt = 0; nt < 4; nt++) mma_bf16(acc[mt][nt], al[mt], bh[nt]);
            }
        }

        if (more) {
            sts_a(buf ^ 1, pa);
            cp_async_wait0();
            __syncthreads();
            buf ^= 1;
        }
    }

    // ---------------- epilogue ----------------
#pragma unroll
    for (int nt = 0; nt < 4; nt++) {
        const int c0 = bn + wn + 8 * nt + 2 * ft;
        float b0 = 0.f, b1 = 0.f;
        if (HASBIAS) {
            b0 = __ldg(bias + c0);
            b1 = __ldg(bias + c0 + 1);
        }
#pragma unroll
        for (int mt = 0; mt < 4; mt++) {
            const int r0 = bm + wm + 16 * mt + fg;
            const int r1 = r0 + 8;
            float o00 = acc[mt][nt][0] + b0;
            float o01 = acc[mt][nt][1] + b1;
            float o10 = acc[mt][nt][2] + b0;
            float o11 = acc[mt][nt][3] + b1;
            if (CACC) {
                if (r0 < M) {
                    float2 ci = *(const float2*)(Cin + (size_t)r0 * N + c0);
                    o00 += ci.x;
                    o01 += ci.y;
                }
                if (r1 < M) {
                    float2 ci = *(const float2*)(Cin + (size_t)r1 * N + c0);
                    o10 += ci.x;
                    o11 += ci.y;
                }
            }
            if (RELU) {
                o00 = fmaxf(o00, 0.f); o01 = fmaxf(o01, 0.f);
                o10 = fmaxf(o10, 0.f); o11 = fmaxf(o11, 0.f);
            }
            if (r0 < M) *(float2*)(Cout + (size_t)r0 * N + c0) = make_float2(o00, o01);
            if (r1 < M) *(float2*)(Cout + (size_t)r1 * N + c0) = make_float2(o10, o11);
        }
    }
}

// ---------------- decode ----------------
__global__ void decode_kernel(const int* __restrict__ ls,
                              const int* __restrict__ ld,
                              float* __restrict__ out) {
    int gt = blockIdx.x * blockDim.x + threadIdx.x;
    int i = gt >> 5;
    int lane = gt & 31;
    if (i >= NL) return;
    int a = __ldg(ls + i);
    int b = __ldg(ld + i);
    float4 u = ((const float4*)g_z_user)[a * 32 + lane];
    float4 v = ((const float4*)g_z_item)[b * 32 + lane];
    float s = u.x * v.x + u.y * v.y + u.z * v.z + u.w * v.w;
#pragma unroll
    for (int o = 16; o > 0; o >>= 1) s += __shfl_down_sync(0xffffffffu, s, o);
    if (lane == 0) {
        out[i] = -s;
        out[NL + i] = s;
    }
}

// ---------------- host launch ----------------
extern "C" void kernel_launch(void* const* d_in, const int* in_sizes, int n_in,
                              void* d_out, int out_size) {
    const float* x_user = (const float*)d_in[0];
    const float* x_item = (const float*)d_in[1];
    const float* Wl1_ui = (const float*)d_in[2];
    const float* Wr1_ui = (const float*)d_in[3];
    const float* b1_ui  = (const float*)d_in[4];
    const float* Wl1_iu = (const float*)d_in[5];
    const float* Wr1_iu = (const float*)d_in[6];
    const float* b1_iu  = (const float*)d_in[7];
    const float* Wl2_ui = (const float*)d_in[8];
    const float* Wr2_ui = (const float*)d_in[9];
    const float* b2_ui  = (const float*)d_in[10];
    const float* Wl2_iu = (const float*)d_in[11];
    const float* Wr2_iu = (const float*)d_in[12];
    const float* b2_iu  = (const float*)d_in[13];
    const int* src_u     = (const int*)d_in[14];
    const int* dst_i     = (const int*)d_in[15];
    const int* label_src = (const int*)d_in[16];
    const int* label_dst = (const int*)d_in[17];

    float *a1i, *a1u, *hi, *hu, *c2i, *c2u, *zi, *zu;
    uint32_t *pwh, *pwl;
    cudaGetSymbolAddress((void**)&a1i, g_agg1_item);
    cudaGetSymbolAddress((void**)&a1u, g_agg1_user);
    cudaGetSymbolAddress((void**)&hi, g_h_item);
    cudaGetSymbolAddress((void**)&hu, g_h_user);
    cudaGetSymbolAddress((void**)&c2i, g_acc2_item);
    cudaGetSymbolAddress((void**)&c2u, g_acc2_user);
    cudaGetSymbolAddress((void**)&zi, g_z_item);
    cudaGetSymbolAddress((void**)&zu, g_z_user);
    cudaGetSymbolAddress((void**)&pwh, g_pwh);
    cudaGetSymbolAddress((void**)&pwl, g_pwl);

    cudaFuncSetAttribute(gemm_pp32<128, 256, true, true, false, true>,
                         cudaFuncAttributeMaxDynamicSharedMemorySize, GEMM_SMEM_BYTES);
    cudaFuncSetAttribute(gemm_pp32<256, 128, false, false, false, false>,
                         cudaFuncAttributeMaxDynamicSharedMemorySize, GEMM_SMEM_BYTES);
    cudaFuncSetAttribute(gemm_pp32<256, 128, false, true, true, false>,
                         cudaFuncAttributeMaxDynamicSharedMemorySize, GEMM_SMEM_BYTES);

    const int MT_U = (N_USER + 127) / 128;   // 391
    const int AGG_THREADS = (N_ITEM + N_USER) * 32;

    // idx0: zero CSR counters
    zero_cnt<<<(N_USER + 255) / 256, 256>>>();

    // idx1: degree histogram
    hist_k<<<(NE + 255) / 256, 256>>>(src_u, dst_i);

    // idx2: exclusive scans (item + user)
    scan_k<<<2, 1024>>>();

    // idx3 (profiler capture slot): CSR fill
    fill_k<<<(NE + 255) / 256, 256>>>(src_u, dst_i);

    // idx4: pack weights (frag-tuple layout)
    pack_w<<<(PACK_WORK + 255) / 256, 256>>>(Wl1_ui, Wr1_ui, Wl1_iu, Wr1_iu,
                                             Wl2_ui, Wr2_ui, Wl2_iu, Wr2_iu);

    // idx5: layer-1 mean aggregation (both directions)
    agg_dual<<<(AGG_THREADS + 255) / 256, 256>>>(x_user, x_item, a1i, a1u);

    // idx6: layer-1 dual GEMM -> h (fp32)
    {
        GP P;
        P.M[0] = N_USER;              P.M[1] = N_ITEM;
        P.A1[0] = a1u;                P.A1[1] = a1i;
        P.A2[0] = x_user;             P.A2[1] = x_item;
        P.PW1h[0] = pwh + 2 * 16384;  P.PW1h[1] = pwh + 0 * 16384;
        P.PW1l[0] = pwl + 2 * 16384;  P.PW1l[1] = pwl + 0 * 16384;
        P.PW2h[0] = pwh + 3 * 16384;  P.PW2h[1] = pwh + 1 * 16384;
        P.PW2l[0] = pwl + 3 * 16384;  P.PW2l[1] = pwl + 1 * 16384;
        P.bias[0] = b1_iu;            P.bias[1] = b1_ui;
        P.Cin[0] = nullptr;           P.Cin[1] = nullptr;
        P.Cf[0] = hu;                 P.Cf[1] = hi;
        gemm_pp32<128, 256, true, true, false, true>
            <<<dim3(2, MT_U, 2), 256, GEMM_SMEM_BYTES>>>(P);
    }

    // idx7: p = h @ Wl2 dual GEMM (into reused agg buffers)
    {
        GP P;
        P.M[0] = N_USER;              P.M[1] = N_ITEM;
        P.A1[0] = hu;                 P.A1[1] = hi;
        P.A2[0] = nullptr;            P.A2[1] = nullptr;
        P.PW1h[0] = pwh + 4 * 16384;  P.PW1h[1] = pwh + 6 * 16384;
        P.PW1l[0] = pwl + 4 * 16384;  P.PW1l[1] = pwl + 6 * 16384;
        P.PW2h[0] = nullptr;          P.PW2h[1] = nullptr;
        P.PW2l[0] = nullptr;          P.PW2l[1] = nullptr;
        P.bias[0] = nullptr;          P.bias[1] = nullptr;
        P.Cin[0] = nullptr;           P.Cin[1] = nullptr;
        P.Cf[0] = a1u;                P.Cf[1] = a1i;
        gemm_pp32<256, 128, false, false, false, false>
            <<<dim3(1, MT_U, 2), 256, GEMM_SMEM_BYTES>>>(P);
    }

    // idx8: layer-2 mean aggregation of transformed features
    agg_dual<<<(AGG_THREADS + 255) / 256, 256>>>(a1u, a1i, c2i, c2u);

    // idx9: z = acc2 + h @ Wr2 + b2 dual GEMM
    {
        GP P;
        P.M[0] = N_USER;              P.M[1] = N_ITEM;
        P.A1[0] = hu;                 P.A1[1] = hi;
        P.A2[0] = nullptr;            P.A2[1] = nullptr;
        P.PW1h[0] = pwh + 7 * 16384;  P.PW1h[1] = pwh + 5 * 16384;
        P.PW1l[0] = pwl + 7 * 16384;  P.PW1l[1] = pwl + 5 * 16384;
        P.PW2h[0] = nullptr;          P.PW2h[1] = nullptr;
        P.PW2l[0] = nullptr;          P.PW2l[1] = nullptr;
        P.bias[0] = b2_iu;            P.bias[1] = b2_ui;
        P.Cin[0] = c2u;               P.Cin[1] = c2i;
        P.Cf[0] = zu;                 P.Cf[1] = zi;
        gemm_pp32<256, 128, false, true, true, false>
            <<<dim3(1, MT_U, 2), 256, GEMM_SMEM_BYTES>>>(P);
    }

    // idx10: decode
    {
        long long threads = (long long)NL * 32;
        decode_kernel<<<(int)((threads + 255) / 256), 256>>>(label_src, label_dst, (float*)d_out);
    }
}